// round 6
// baseline (speedup 1.0000x reference)
#include <cuda_runtime.h>
#include <cstdint>

// ---------------- problem constants ----------------
#define NBLK 148
#define NTHR 256
#define BB   256
#define NC   3072            // compact gate width (i, gg, o) -- f gate is dead
#define TT   256
#define VV   130
#define BH   (256*1024)
#define GS   (256*3072)

// ---------------- persistent device scratch ----------------
__device__ float d_cT   [16*256*512];
__device__ float d_cPrev[16*256*512];
__device__ float d_hid  [16*256*1024];
__device__ float d_A1   [3*16*256*3072];
__device__ float d_CU   [16*256*3072];
__device__ float d_C2   [3*16*256*3072];
__device__ float d_E    [3*130*3072];
__device__ float d_nb1  [3*3072];
__device__ float d_h1   [3*256*1024];
__device__ float d_h2   [3*256*1024];
__device__ float d_ctxs [3*256*1024];
__device__ float d_uold [3*256*1024];
__device__ float d_unew [2*256*1024];
__device__ float d_s    [3*256*3072];
__device__ float d_sn   [2*256*3072];
__device__ float d_g    [3*256*3072];

// ---------------- grid barrier (replay-safe, sense via generation) ----------
__device__ unsigned int g_arrive;
__device__ unsigned int g_gen;

__device__ __forceinline__ void gsync()
{
    __threadfence();
    __syncthreads();
    if (threadIdx.x == 0) {
        volatile unsigned int* vg = &g_gen;
        unsigned int g = *vg;
        if (atomicAdd(&g_arrive, 1u) == (unsigned)(gridDim.x - 1)) {
            g_arrive = 0;
            __threadfence();
            *vg = g + 1u;
        } else {
            while (*vg == g) __nanosleep(32);
        }
        __threadfence();
    }
    __syncthreads();
}

// ---------------- f32x2 helpers ----------------
__device__ __forceinline__ void fma2(unsigned long long &c, unsigned long long a,
                                     unsigned long long b) {
    asm("fma.rn.f32x2 %0, %1, %2, %0;" : "+l"(c) : "l"(a), "l"(b));
}
__device__ __forceinline__ unsigned long long dup2(float a) {
    unsigned long long r;
    asm("mov.b64 %0, {%1, %1};" : "=l"(r) : "f"(a));
    return r;
}
__device__ __forceinline__ void unpack2(unsigned long long v, float &lo, float &hi) {
    asm("mov.b64 {%0, %1}, %2;" : "=f"(lo), "=f"(hi) : "l"(v));
}

// ---------------- generic fused GEMM stage ----------------
struct GP {
    const float* A;  long long lda,  Az;
    const float* B;  long long ldb,  Bz;
    const float* A2; long long lda2, A2z;
    const float* B2; long long ldb2, B2z;
    int K, K2, M, N, zc, compact, epi;   // epi: 0 none, 1 tanh
    float* C; long long ldc, Cz;
    const float* add0; long long add0z;
    const float* add1;
    const float* add2;
    const float* bias; long long biasz; int biasCompact;
    const float* Eg;  long long Egz;
    const int*  tok;  long long tokz;  int tokstride;
};

// TM x 128 tile, thread computes (TM/16) x 8 outputs. 256 threads: tx=n, ty=m.
template<int TM>
__device__ __forceinline__ void run_mm(const float* A, long long lda, int M, int m0,
                                       const float* Bb, long long ldb, int N, int n0, int K,
                                       float* As, float* Bs,
                                       unsigned long long (*acc)[4],
                                       int tid, int tx, int ty)
{
    const int MI = TM / 16;
    for (int k0 = 0; k0 < K; k0 += 16) {
        // stage A tile: TM rows x 16 k  (TM*4 float4s)
#pragma unroll
        for (int j = tid; j < TM * 4; j += NTHR) {
            int row = j >> 2, kq = (j & 3) << 2;
            float4 v = (m0 + row < M)
                ? *(const float4*)(A + (long long)(m0 + row) * lda + k0 + kq)
                : make_float4(0.f, 0.f, 0.f, 0.f);
            As[(kq + 0) * TM + row] = v.x;
            As[(kq + 1) * TM + row] = v.y;
            As[(kq + 2) * TM + row] = v.z;
            As[(kq + 3) * TM + row] = v.w;
        }
        // stage B tile: 128 rows x 16 k  (512 float4s)
#pragma unroll
        for (int j = tid; j < 512; j += NTHR) {
            int row = j >> 2, kq = (j & 3) << 2;
            float4 v = (n0 + row < N)
                ? *(const float4*)(Bb + (long long)row * ldb + k0 + kq)
                : make_float4(0.f, 0.f, 0.f, 0.f);
            Bs[(kq + 0) * 128 + row] = v.x;
            Bs[(kq + 1) * 128 + row] = v.y;
            Bs[(kq + 2) * 128 + row] = v.z;
            Bs[(kq + 3) * 128 + row] = v.w;
        }
        __syncthreads();
#pragma unroll
        for (int kk = 0; kk < 16; kk++) {
            unsigned long long b[4];
#pragma unroll
            for (int jj = 0; jj < 4; jj++)
                b[jj] = *(const unsigned long long*)&Bs[kk * 128 + tx * 8 + jj * 2];
            float av[MI];
#pragma unroll
            for (int p = 0; p < MI / 2; p++) {
                unsigned long long ap =
                    *(const unsigned long long*)&As[kk * TM + ty * MI + 2 * p];
                unpack2(ap, av[2 * p], av[2 * p + 1]);
            }
#pragma unroll
            for (int mi = 0; mi < MI; mi++) {
                unsigned long long a2 = dup2(av[mi]);
                fma2(acc[mi][0], a2, b[0]);
                fma2(acc[mi][1], a2, b[1]);
                fma2(acc[mi][2], a2, b[2]);
                fma2(acc[mi][3], a2, b[3]);
            }
        }
        __syncthreads();
    }
}

template<int TM>
__device__ void gemm_stage(const GP& g, float* As, float* Bs)
{
    const int MI = TM / 16;
    int mT = (g.M + TM - 1) / TM;
    int nT = (g.N + 127) >> 7;
    int total = g.zc * mT * nT;
    int tid = threadIdx.x;
    int tx = tid & 15, ty = tid >> 4;

    for (int tile = blockIdx.x; tile < total; tile += gridDim.x) {
        int z  = tile / (mT * nT);
        int r  = tile - z * (mT * nT);
        int mi0 = r / nT;
        int m0 = mi0 * TM;
        int n0 = (r - mi0 * nT) << 7;
        int noff = (g.compact && n0 >= 1024) ? 1024 : 0;

        unsigned long long acc[MI][4];
#pragma unroll
        for (int i = 0; i < MI; i++)
#pragma unroll
            for (int j = 0; j < 4; j++) acc[i][j] = 0ull;

        {
            const float* A  = g.A + (long long)z * g.Az;
            const float* Bb = g.B + (long long)z * g.Bz + (long long)(n0 + noff) * g.ldb;
            run_mm<TM>(A, g.lda, g.M, m0, Bb, g.ldb, g.N, n0, g.K, As, Bs, acc, tid, tx, ty);
        }
        if (g.A2) {
            const float* A  = g.A2 + (long long)z * g.A2z;
            const float* Bb = g.B2 + (long long)z * g.B2z + (long long)(n0 + noff) * g.ldb2;
            run_mm<TM>(A, g.lda2, g.M, m0, Bb, g.ldb2, g.N, n0, g.K2, As, Bs, acc, tid, tx, ty);
        }

        float* C = g.C + (long long)z * g.Cz;
#pragma unroll
        for (int mi = 0; mi < MI; mi++) {
            int m = m0 + ty * MI + mi;
            if (m >= g.M) continue;
            float cv[8];
#pragma unroll
            for (int jj = 0; jj < 4; jj++)
                unpack2(acc[mi][jj], cv[2 * jj], cv[2 * jj + 1]);
            long long token = 0;
            if (g.Eg) token = g.tok[(long long)z * g.tokz + (long long)m * g.tokstride];
#pragma unroll
            for (int nj = 0; nj < 8; nj++) {
                int n = n0 + tx * 8 + nj;
                if (n >= g.N) continue;
                float v = cv[nj];
                if (g.add0) v += g.add0[(long long)z * g.add0z + (long long)m * g.N + n];
                if (g.add1) v += g.add1[(long long)m * g.N + n];
                if (g.add2) v += g.add2[(long long)m * g.N + n];
                if (g.bias) v += g.bias[(long long)z * g.biasz + (g.biasCompact ? (n + noff) : n)];
                if (g.Eg)   v += g.Eg[(long long)z * g.Egz + token * g.N + n];
                if (g.epi == 1) v = tanhf(v);
                C[(long long)m * g.ldc + n] = v;
            }
        }
    }
}

// gate: h = sigmoid(o) * tanh(sigmoid(i) * tanh(gg)); compact layout [i|gg|o]
__device__ void gate_stage(const float* gsrc, long long gz, int zc,
                           float* dst0, long long d0z, float* dst1, long long d1z)
{
    int total = zc << 18;
    for (int idx = blockIdx.x * NTHR + threadIdx.x; idx < total; idx += gridDim.x * NTHR) {
        int z   = idx >> 18;
        int rem = idx & ((1 << 18) - 1);
        int m = rem >> 10, j = rem & 1023;
        const float* gp = gsrc + (long long)z * gz + (long long)m * NC;
        float gi = gp[j], gg = gp[1024 + j], go = gp[2048 + j];
        float si = 1.f / (1.f + expf(-gi));
        float so = 1.f / (1.f + expf(-go));
        float v  = so * tanhf(si * tanhf(gg));
        long long o = (long long)z * d0z + (long long)m * 1024 + j;
        dst0[o] = v;
        if (dst1) dst1[(long long)z * d1z + (long long)m * 1024 + j] = v;
    }
}

__device__ void reset_stage(const float* hid)
{
    for (int idx = blockIdx.x * NTHR + threadIdx.x; idx < (1 << 18);
         idx += gridDim.x * NTHR) {
        float v = hid[idx];
        d_h1[idx] = v; d_h1[BH + idx] = v; d_h1[2 * BH + idx] = v;
        d_h2[idx] = v; d_h2[BH + idx] = v; d_h2[2 * BH + idx] = v;
        d_ctxs[2 * BH + idx] = v;
    }
}

__device__ void prep_stage(const float* c)
{
    for (int idx = blockIdx.x * NTHR + threadIdx.x; idx < (16 * 256 * 512);
         idx += gridDim.x * NTHR) {
        int ptr = idx >> 17;
        int rem = idx & 131071;
        int b = rem >> 9, k = rem & 511;
        d_cT[idx] = c[((b << 4) + ptr) * 512 + k];
        int pm = ptr > 0 ? ptr - 1 : 0;
        d_cPrev[idx] = c[((b << 4) + pm) * 512 + k];
    }
}

__device__ void nb1_stage(const float* emb, const float* W1ih, const float* b1)
{
    for (int idx = blockIdx.x * NTHR + threadIdx.x; idx < 3 * 3072;
         idx += gridDim.x * NTHR) {
        int i = idx / 3072, n = idx - (idx / 3072) * 3072;
        int nfull = n + (n >= 1024 ? 1024 : 0);
        const float* e = emb + (long long)i * 130 * 512;            // v = 0 row
        const float* w = W1ih + ((long long)i * 4096 + nfull) * 1024;
        float s = b1[i * 4096 + nfull];
        for (int k = 0; k < 512; k++) s += e[k] * w[k];
        d_nb1[idx] = s;
    }
}

// ---------------- the single persistent kernel ----------------
__global__ void __launch_bounds__(NTHR, 1)
mega_kernel(const float* c, const float* W1ih, const float* W1hh, const float* b1,
            const float* cWih, const float* cWhh, const float* cb,
            const float* W2ih, const float* W2hh, const float* b2,
            const float* outW, const float* outb,
            const float* hidW, const float* hidb,
            const float* emb, const int* tgt, float* out)
{
    __shared__ __align__(16) float As[16 * 128];
    __shared__ __align__(16) float Bs[16 * 128];

    // ---- phase 0: transpose + notes0 hoist ----
    prep_stage(c);
    nb1_stage(emb, W1ih, b1);
    gsync();

    // ---- phase 1: all per-bar hoisted GEMMs ----
    { // hidden[ptr] = tanh(cPrev @ hidW^T + hidb)
        GP g = {};
        g.A = d_cPrev; g.lda = 512; g.B = hidW; g.ldb = 512;
        g.K = 512; g.M = 4096; g.N = 1024; g.zc = 1; g.epi = 1;
        g.C = d_hid; g.ldc = 1024;
        g.bias = hidb;
        gemm_stage<128>(g, As, Bs);
    }
    { // A1[i][ptr] = nb1[i] + cT @ W1ih[i][:,512:]^T
        GP g = {};
        g.A = d_cT; g.lda = 512;
        g.B = W1ih + 512; g.ldb = 1024; g.Bz = (long long)4096 * 1024;
        g.K = 512; g.M = 4096; g.N = NC; g.zc = 3; g.compact = 1;
        g.C = d_A1; g.ldc = NC; g.Cz = (long long)16 * GS;
        g.bias = d_nb1; g.biasz = NC;
        gemm_stage<128>(g, As, Bs);
    }
    { // CU[ptr] = cT @ W1ih[1][:,512:]^T + b1[1]
        GP g = {};
        g.A = d_cT; g.lda = 512;
        g.B = W1ih + (long long)4096 * 1024 + 512; g.ldb = 1024;
        g.K = 512; g.M = 4096; g.N = NC; g.zc = 1; g.compact = 1;
        g.C = d_CU; g.ldc = NC;
        g.bias = b1 + 4096; g.biasCompact = 1;
        gemm_stage<128>(g, As, Bs);
    }
    { // C2[i][ptr] = cT @ W2ih[i][:,1024:]^T + b2[i]
        GP g = {};
        g.A = d_cT; g.lda = 512;
        g.B = W2ih + 1024; g.ldb = 1536; g.Bz = (long long)4096 * 1536;
        g.K = 512; g.M = 4096; g.N = NC; g.zc = 3; g.compact = 1;
        g.C = d_C2; g.ldc = NC; g.Cz = (long long)16 * GS;
        g.bias = b2; g.biasz = 4096; g.biasCompact = 1;
        gemm_stage<128>(g, As, Bs);
    }
    { // E = emb @ W1ih[1][:, :512]^T
        GP g = {};
        g.A = emb; g.lda = 512;
        g.B = W1ih + (long long)4096 * 1024; g.ldb = 1024;
        g.K = 512; g.M = 390; g.N = NC; g.zc = 1; g.compact = 1;
        g.C = d_E; g.ldc = NC;
        gemm_stage<128>(g, As, Bs);
    }
    gsync();

    // ---- time loop ----
    for (int t = 0; t < TT; t++) {
        int ptr = t >> 4;
        if ((t & 15) == 0) {
            reset_stage(d_hid + (long long)ptr * BH);
            gsync();
        }

        { // g = A1[.,ptr] + h1 @ W1hh^T        (144 tiles = 1 wave)
            GP g = {};
            g.A = d_h1; g.lda = 1024; g.Az = BH;
            g.B = W1hh; g.ldb = 1024; g.Bz = (long long)4096 * 1024;
            g.K = 1024; g.M = BB; g.N = NC; g.zc = 3; g.compact = 1;
            g.C = d_g; g.ldc = NC; g.Cz = GS;
            g.add0 = d_A1 + (long long)ptr * GS; g.add0z = (long long)16 * GS;
            gemm_stage<128>(g, As, Bs);
        }
        gsync();
        gate_stage(d_g, GS, 3, d_h1, BH, d_uold, BH);
        gsync();

        { // s[i] = uold[i] @ ctxWih slice^T    (144 tiles)
            GP g = {};
            g.A = d_uold; g.lda = 1024; g.Az = BH;
            g.B = cWih; g.ldb = NC; g.Bz = 1024;
            g.K = 1024; g.M = BB; g.N = NC; g.zc = 3; g.compact = 1;
            g.C = d_s; g.ldc = NC; g.Cz = GS;
            gemm_stage<128>(g, As, Bs);
        }
        { // gu[i] = E[i][tok] + CU[ptr] + uold[i] @ W1hh[1]^T   (i = 0,1)
            GP g = {};
            g.A = d_uold; g.lda = 1024; g.Az = BH;
            g.B = W1hh + (long long)4096 * 1024; g.ldb = 1024;
            g.K = 1024; g.M = BB; g.N = NC; g.zc = 2; g.compact = 1;
            g.C = d_g; g.ldc = NC; g.Cz = GS;
            g.add0 = d_CU + (long long)ptr * GS; g.add0z = 0;
            g.Eg = d_E; g.Egz = (long long)130 * NC;
            g.tok = tgt + t; g.tokz = 65536; g.tokstride = 256;
            gemm_stage<128>(g, As, Bs);
        }
        gsync();
        gate_stage(d_g, GS, 2, d_unew, BH, (float*)0, 0);
        gsync();

        { // sn[i] = unew[i] @ ctxWih slice^T  (i = 0,1)
            GP g = {};
            g.A = d_unew; g.lda = 1024; g.Az = BH;
            g.B = cWih; g.ldb = NC; g.Bz = 1024;
            g.K = 1024; g.M = BB; g.N = NC; g.zc = 2; g.compact = 1;
            g.C = d_sn; g.ldc = NC; g.Cz = GS;
            gemm_stage<128>(g, As, Bs);
        }
        { // ctx update 0 (shares phase with sn)
            GP g = {};
            g.A = d_ctxs + 2 * (long long)BH; g.lda = 1024;
            g.B = cWhh; g.ldb = 1024;
            g.K = 1024; g.M = BB; g.N = NC; g.zc = 1; g.compact = 1;
            g.C = d_g; g.ldc = NC;
            g.add0 = d_s; g.add0z = 0;
            g.add1 = d_s + GS; g.add2 = d_s + 2 * (long long)GS;
            g.bias = cb; g.biasCompact = 1;
            gemm_stage<64>(g, As, Bs);
        }
        gsync();
        gate_stage(d_g, 0, 1, d_ctxs, 0, (float*)0, 0);
        gsync();

        { // ctx update 1
            GP g = {};
            g.A = d_ctxs; g.lda = 1024;
            g.B = cWhh; g.ldb = 1024;
            g.K = 1024; g.M = BB; g.N = NC; g.zc = 1; g.compact = 1;
            g.C = d_g; g.ldc = NC;
            g.add0 = d_sn; g.add0z = 0;
            g.add1 = d_s + GS; g.add2 = d_s + 2 * (long long)GS;
            g.bias = cb; g.biasCompact = 1;
            gemm_stage<64>(g, As, Bs);
        }
        gsync();
        gate_stage(d_g, 0, 1, d_ctxs + BH, 0, (float*)0, 0);
        gsync();

        { // ctx update 2
            GP g = {};
            g.A = d_ctxs + (long long)BH; g.lda = 1024;
            g.B = cWhh; g.ldb = 1024;
            g.K = 1024; g.M = BB; g.N = NC; g.zc = 1; g.compact = 1;
            g.C = d_g; g.ldc = NC;
            g.add0 = d_sn; g.add0z = 0;
            g.add1 = d_sn + GS; g.add2 = d_s + 2 * (long long)GS;
            g.bias = cb; g.biasCompact = 1;
            gemm_stage<64>(g, As, Bs);
        }
        gsync();
        gate_stage(d_g, 0, 1, d_ctxs + 2 * (long long)BH, 0, (float*)0, 0);
        gsync();

        { // g2[i] = ctxs[i] @ W2ih[i][:, :1024]^T + h2[i] @ W2hh[i]^T + C2[i][ptr]
            GP g = {};
            g.A = d_ctxs; g.lda = 1024; g.Az = BH;
            g.B = W2ih; g.ldb = 1536; g.Bz = (long long)4096 * 1536;
            g.K = 1024;
            g.A2 = d_h2; g.lda2 = 1024; g.A2z = BH;
            g.B2 = W2hh; g.ldb2 = 1024; g.B2z = (long long)4096 * 1024;
            g.K2 = 1024;
            g.M = BB; g.N = NC; g.zc = 3; g.compact = 1;
            g.C = d_g; g.ldc = NC; g.Cz = GS;
            g.add0 = d_C2 + (long long)ptr * GS; g.add0z = (long long)16 * GS;
            gemm_stage<128>(g, As, Bs);
        }
        gsync();
        gate_stage(d_g, GS, 3, d_h2, BH, (float*)0, 0);
        gsync();

        { // out[i][:,t,:] = (uold[i] + h2[i]) @ outW[i]^T + outb[i]
            GP g = {};
            g.A = d_uold; g.lda = 1024; g.Az = BH;
            g.B = outW; g.ldb = 1024; g.Bz = (long long)130 * 1024;
            g.K = 1024;
            g.A2 = d_h2; g.lda2 = 1024; g.A2z = BH;
            g.B2 = outW; g.ldb2 = 1024; g.B2z = (long long)130 * 1024;
            g.K2 = 1024;
            g.M = BB; g.N = VV; g.zc = 3;
            g.C = out + (long long)t * VV; g.ldc = (long long)TT * VV;
            g.Cz = (long long)BB * TT * VV;
            g.bias = outb; g.biasz = VV;
            gemm_stage<64>(g, As, Bs);
        }
        gsync();   // protects uold/h2 (read by OUT) from next step's writers
    }
}

// ---------------- host ----------------
extern "C" void kernel_launch(void* const* d_in, const int* in_sizes, int n_in,
                              void* d_out, int out_size)
{
    (void)in_sizes; (void)n_in; (void)out_size;
    mega_kernel<<<NBLK, NTHR>>>(
        (const float*)d_in[0],  (const float*)d_in[1],  (const float*)d_in[2],
        (const float*)d_in[3],  (const float*)d_in[4],  (const float*)d_in[5],
        (const float*)d_in[6],  (const float*)d_in[7],  (const float*)d_in[8],
        (const float*)d_in[9],  (const float*)d_in[10], (const float*)d_in[11],
        (const float*)d_in[12], (const float*)d_in[13], (const float*)d_in[14],
        (const int*)d_in[15],   (float*)d_out);
}

// round 7
// speedup vs baseline: 1.2916x; 1.2916x over previous
#include <cuda_runtime.h>
#include <cstdint>

// ---------------- problem constants ----------------
#define NBLK 148
#define NTHR 256
#define BB   256
#define NC   3072            // compact gate width (i, gg, o) -- f gate is dead
#define TT   256
#define VV   130
#define BH   (256*1024)
#define GS   (256*3072)

// ---------------- persistent device scratch ----------------
__device__ float d_cT   [16*256*512];
__device__ float d_cPrev[16*256*512];
__device__ float d_hid  [16*256*1024];
__device__ float d_A1   [3*16*256*3072];
__device__ float d_CU   [16*256*3072];
__device__ float d_C2   [3*16*256*3072];
__device__ float d_E    [3*130*3072];
__device__ float d_nb1  [3*3072];
__device__ float d_h1   [3*256*1024];
__device__ float d_h2   [3*256*1024];
__device__ float d_ctxs [3*256*1024];
__device__ float d_uold [3*256*1024];
__device__ float d_unew [2*256*1024];
__device__ float d_s    [3*256*3072];
__device__ float d_sn   [2*256*3072];
__device__ float d_g    [3*256*3072];

// ---------------- grid barrier (replay-safe, sense via generation) ----------
__device__ unsigned int g_arrive;
__device__ unsigned int g_gen;

__device__ __forceinline__ void gsync()
{
    __threadfence();
    __syncthreads();
    if (threadIdx.x == 0) {
        volatile unsigned int* vg = &g_gen;
        unsigned int g = *vg;
        if (atomicAdd(&g_arrive, 1u) == (unsigned)(gridDim.x - 1)) {
            g_arrive = 0;
            __threadfence();
            *vg = g + 1u;
        } else {
            while (*vg == g) __nanosleep(32);
        }
        __threadfence();
    }
    __syncthreads();
}

// ---------------- f32x2 helpers ----------------
__device__ __forceinline__ void fma2(unsigned long long &c, unsigned long long a,
                                     unsigned long long b) {
    asm("fma.rn.f32x2 %0, %1, %2, %0;" : "+l"(c) : "l"(a), "l"(b));
}
__device__ __forceinline__ unsigned long long dup2(float a) {
    unsigned long long r;
    asm("mov.b64 %0, {%1, %1};" : "=l"(r) : "f"(a));
    return r;
}
__device__ __forceinline__ void unpack2(unsigned long long v, float &lo, float &hi) {
    asm("mov.b64 {%0, %1}, %2;" : "=f"(lo), "=f"(hi) : "l"(v));
}

// ---------------- generic fused GEMM stage ----------------
struct GP {
    const float* A;  long long lda,  Az;
    const float* B;  long long ldb,  Bz;
    const float* A2; long long lda2, A2z;
    const float* B2; long long ldb2, B2z;
    int K, K2, M, N, zc, compact, epi;   // epi: 0 none, 1 tanh
    float* C; long long ldc, Cz;
    const float* add0; long long add0z;
    const float* add1;
    const float* add2;
    const float* bias; long long biasz; int biasCompact;
    const float* Eg;  long long Egz;
    const int*  tok;  long long tokz;  int tokstride;
};

// ---- staging: global -> regs (guarded, coalesced) ----
template<int TM>
__device__ __forceinline__ void ld_regs(const float* A, long long lda, int M, int m0,
                                        const float* Bb, long long ldb, int N, int n0,
                                        int k0, float4* ra, float4* rb, int tid)
{
    const int AR = TM / 64;
#pragma unroll
    for (int i = 0; i < AR; i++) {
        int j = tid + 256 * i, row = j >> 2, kq = (j & 3) << 2;
        ra[i] = (m0 + row < M)
            ? *(const float4*)(A + (long long)(m0 + row) * lda + k0 + kq)
            : make_float4(0.f, 0.f, 0.f, 0.f);
    }
#pragma unroll
    for (int i = 0; i < 2; i++) {
        int j = tid + 256 * i, row = j >> 2, kq = (j & 3) << 2;
        rb[i] = (n0 + row < N)
            ? *(const float4*)(Bb + (long long)row * ldb + k0 + kq)
            : make_float4(0.f, 0.f, 0.f, 0.f);
    }
}

// ---- regs -> smem, k-major transposed layout [kk][row] ----
template<int TM>
__device__ __forceinline__ void st_smem(float* Sa, float* Sb,
                                        const float4* ra, const float4* rb, int tid)
{
    const int AR = TM / 64;
#pragma unroll
    for (int i = 0; i < AR; i++) {
        int j = tid + 256 * i, row = j >> 2, kq = (j & 3) << 2;
        Sa[(kq + 0) * TM + row] = ra[i].x;
        Sa[(kq + 1) * TM + row] = ra[i].y;
        Sa[(kq + 2) * TM + row] = ra[i].z;
        Sa[(kq + 3) * TM + row] = ra[i].w;
    }
#pragma unroll
    for (int i = 0; i < 2; i++) {
        int j = tid + 256 * i, row = j >> 2, kq = (j & 3) << 2;
        Sb[(kq + 0) * 128 + row] = rb[i].x;
        Sb[(kq + 1) * 128 + row] = rb[i].y;
        Sb[(kq + 2) * 128 + row] = rb[i].z;
        Sb[(kq + 3) * 128 + row] = rb[i].w;
    }
}

// ---- conflict-free compute over one 16-k slice ----
template<int TM>
__device__ __forceinline__ void compute16(const float* Sa, const float* Sb,
                                          unsigned long long (*acc)[4], int tx, int ty)
{
    const int MI = TM / 16;
#pragma unroll
    for (int kk = 0; kk < 16; kk++) {
        // B fragment: 2x LDS.128, lanes cover 512B contiguous -> conflict-free
        ulonglong2 b01 = *(const ulonglong2*)&Sb[kk * 128 + tx * 8];
        ulonglong2 b23 = *(const ulonglong2*)&Sb[kk * 128 + tx * 8 + 4];
        // A fragment: LDS.128 broadcast (2 distinct addrs per warp)
        float av[MI];
#pragma unroll
        for (int p = 0; p < MI / 4; p++) {
            ulonglong2 ap = *(const ulonglong2*)&Sa[kk * TM + ty * MI + 4 * p];
            unpack2(ap.x, av[4 * p + 0], av[4 * p + 1]);
            unpack2(ap.y, av[4 * p + 2], av[4 * p + 3]);
        }
#pragma unroll
        for (int mi = 0; mi < MI; mi++) {
            unsigned long long a2 = dup2(av[mi]);
            fma2(acc[mi][0], b01.x, a2);
            fma2(acc[mi][1], b01.y, a2);
            fma2(acc[mi][2], b23.x, a2);
            fma2(acc[mi][3], b23.y, a2);
        }
    }
}

// ---- double-buffered mainloop ----
template<int TM>
__device__ __forceinline__ void run_mm(const float* A, long long lda, int M, int m0,
                                       const float* Bb, long long ldb, int N, int n0, int K,
                                       float* As, float* Bs,
                                       unsigned long long (*acc)[4],
                                       int tid, int tx, int ty)
{
    float4 ra[TM / 64], rb[2];
    ld_regs<TM>(A, lda, M, m0, Bb, ldb, N, n0, 0, ra, rb, tid);
    st_smem<TM>(As, Bs, ra, rb, tid);
    __syncthreads();
    int nIter = K >> 4;
    for (int it = 1; it <= nIter; it++) {
        int cur = (it - 1) & 1;
        if (it < nIter)   // issue next slice's global loads before compute
            ld_regs<TM>(A, lda, M, m0, Bb, ldb, N, n0, it << 4, ra, rb, tid);
        compute16<TM>(As + cur * 2048, Bs + cur * 2048, acc, tx, ty);
        __syncthreads();
        if (it < nIter) {
            int nxt = it & 1;
            st_smem<TM>(As + nxt * 2048, Bs + nxt * 2048, ra, rb, tid);
            __syncthreads();
        }
    }
}

template<int TM>
__device__ void gemm_stage(const GP& g, float* As, float* Bs)
{
    const int MI = TM / 16;
    int mT = (g.M + TM - 1) / TM;
    int nT = (g.N + 127) >> 7;
    int total = g.zc * mT * nT;
    int tid = threadIdx.x;
    int tx = tid & 15, ty = tid >> 4;

    for (int tile = blockIdx.x; tile < total; tile += gridDim.x) {
        int z  = tile / (mT * nT);
        int r  = tile - z * (mT * nT);
        int mi0 = r / nT;
        int m0 = mi0 * TM;
        int n0 = (r - mi0 * nT) << 7;
        int noff = (g.compact && n0 >= 1024) ? 1024 : 0;

        unsigned long long acc[MI][4];
#pragma unroll
        for (int i = 0; i < MI; i++)
#pragma unroll
            for (int j = 0; j < 4; j++) acc[i][j] = 0ull;

        {
            const float* A  = g.A + (long long)z * g.Az;
            const float* Bb = g.B + (long long)z * g.Bz + (long long)(n0 + noff) * g.ldb;
            run_mm<TM>(A, g.lda, g.M, m0, Bb, g.ldb, g.N, n0, g.K, As, Bs, acc, tid, tx, ty);
        }
        if (g.A2) {
            const float* A  = g.A2 + (long long)z * g.A2z;
            const float* Bb = g.B2 + (long long)z * g.B2z + (long long)(n0 + noff) * g.ldb2;
            run_mm<TM>(A, g.lda2, g.M, m0, Bb, g.ldb2, g.N, n0, g.K2, As, Bs, acc, tid, tx, ty);
        }

        float* C = g.C + (long long)z * g.Cz;
#pragma unroll
        for (int mi = 0; mi < MI; mi++) {
            int m = m0 + ty * MI + mi;
            if (m >= g.M) continue;
            float cv[8];
#pragma unroll
            for (int jj = 0; jj < 4; jj++)
                unpack2(acc[mi][jj], cv[2 * jj], cv[2 * jj + 1]);
            long long token = 0;
            if (g.Eg) token = g.tok[(long long)z * g.tokz + (long long)m * g.tokstride];
#pragma unroll
            for (int nj = 0; nj < 8; nj++) {
                int n = n0 + tx * 8 + nj;
                if (n >= g.N) continue;
                float v = cv[nj];
                if (g.add0) v += g.add0[(long long)z * g.add0z + (long long)m * g.N + n];
                if (g.add1) v += g.add1[(long long)m * g.N + n];
                if (g.add2) v += g.add2[(long long)m * g.N + n];
                if (g.bias) v += g.bias[(long long)z * g.biasz + (g.biasCompact ? (n + noff) : n)];
                if (g.Eg)   v += g.Eg[(long long)z * g.Egz + token * g.N + n];
                if (g.epi == 1) v = tanhf(v);
                C[(long long)m * g.ldc + n] = v;
            }
        }
    }
}

// gate: h = sigmoid(o) * tanh(sigmoid(i) * tanh(gg)); compact layout [i|gg|o]
__device__ void gate_stage(const float* gsrc, long long gz, int zc,
                           float* dst0, long long d0z, float* dst1, long long d1z)
{
    int total = zc << 18;
    for (int idx = blockIdx.x * NTHR + threadIdx.x; idx < total; idx += gridDim.x * NTHR) {
        int z   = idx >> 18;
        int rem = idx & ((1 << 18) - 1);
        int m = rem >> 10, j = rem & 1023;
        const float* gp = gsrc + (long long)z * gz + (long long)m * NC;
        float gi = gp[j], gg = gp[1024 + j], go = gp[2048 + j];
        float si = 1.f / (1.f + expf(-gi));
        float so = 1.f / (1.f + expf(-go));
        float v  = so * tanhf(si * tanhf(gg));
        long long o = (long long)z * d0z + (long long)m * 1024 + j;
        dst0[o] = v;
        if (dst1) dst1[(long long)z * d1z + (long long)m * 1024 + j] = v;
    }
}

__device__ void reset_stage(const float* hid)
{
    for (int idx = blockIdx.x * NTHR + threadIdx.x; idx < (1 << 18);
         idx += gridDim.x * NTHR) {
        float v = hid[idx];
        d_h1[idx] = v; d_h1[BH + idx] = v; d_h1[2 * BH + idx] = v;
        d_h2[idx] = v; d_h2[BH + idx] = v; d_h2[2 * BH + idx] = v;
        d_ctxs[2 * BH + idx] = v;
    }
}

__device__ void prep_stage(const float* c)
{
    for (int idx = blockIdx.x * NTHR + threadIdx.x; idx < (16 * 256 * 512);
         idx += gridDim.x * NTHR) {
        int ptr = idx >> 17;
        int rem = idx & 131071;
        int b = rem >> 9, k = rem & 511;
        d_cT[idx] = c[((b << 4) + ptr) * 512 + k];
        int pm = ptr > 0 ? ptr - 1 : 0;
        d_cPrev[idx] = c[((b << 4) + pm) * 512 + k];
    }
}

__device__ void nb1_stage(const float* emb, const float* W1ih, const float* b1)
{
    for (int idx = blockIdx.x * NTHR + threadIdx.x; idx < 3 * 3072;
         idx += gridDim.x * NTHR) {
        int i = idx / 3072, n = idx - (idx / 3072) * 3072;
        int nfull = n + (n >= 1024 ? 1024 : 0);
        const float* e = emb + (long long)i * 130 * 512;            // v = 0 row
        const float* w = W1ih + ((long long)i * 4096 + nfull) * 1024;
        float s = b1[i * 4096 + nfull];
        for (int k = 0; k < 512; k++) s += e[k] * w[k];
        d_nb1[idx] = s;
    }
}

// ---------------- the single persistent kernel ----------------
__global__ void __launch_bounds__(NTHR, 1)
mega_kernel(const float* c, const float* W1ih, const float* W1hh, const float* b1,
            const float* cWih, const float* cWhh, const float* cb,
            const float* W2ih, const float* W2hh, const float* b2,
            const float* outW, const float* outb,
            const float* hidW, const float* hidb,
            const float* emb, const int* tgt, float* out)
{
    __shared__ __align__(16) float As[2 * 2048];
    __shared__ __align__(16) float Bs[2 * 2048];

    // ---- phase 0: transpose + notes0 hoist ----
    prep_stage(c);
    nb1_stage(emb, W1ih, b1);
    gsync();

    // ---- phase 1: all per-bar hoisted GEMMs ----
    { // hidden[ptr] = tanh(cPrev @ hidW^T + hidb)
        GP g = {};
        g.A = d_cPrev; g.lda = 512; g.B = hidW; g.ldb = 512;
        g.K = 512; g.M = 4096; g.N = 1024; g.zc = 1; g.epi = 1;
        g.C = d_hid; g.ldc = 1024;
        g.bias = hidb;
        gemm_stage<128>(g, As, Bs);
    }
    { // A1[i][ptr] = nb1[i] + cT @ W1ih[i][:,512:]^T
        GP g = {};
        g.A = d_cT; g.lda = 512;
        g.B = W1ih + 512; g.ldb = 1024; g.Bz = (long long)4096 * 1024;
        g.K = 512; g.M = 4096; g.N = NC; g.zc = 3; g.compact = 1;
        g.C = d_A1; g.ldc = NC; g.Cz = (long long)16 * GS;
        g.bias = d_nb1; g.biasz = NC;
        gemm_stage<128>(g, As, Bs);
    }
    { // CU[ptr] = cT @ W1ih[1][:,512:]^T + b1[1]
        GP g = {};
        g.A = d_cT; g.lda = 512;
        g.B = W1ih + (long long)4096 * 1024 + 512; g.ldb = 1024;
        g.K = 512; g.M = 4096; g.N = NC; g.zc = 1; g.compact = 1;
        g.C = d_CU; g.ldc = NC;
        g.bias = b1 + 4096; g.biasCompact = 1;
        gemm_stage<128>(g, As, Bs);
    }
    { // C2[i][ptr] = cT @ W2ih[i][:,1024:]^T + b2[i]
        GP g = {};
        g.A = d_cT; g.lda = 512;
        g.B = W2ih + 1024; g.ldb = 1536; g.Bz = (long long)4096 * 1536;
        g.K = 512; g.M = 4096; g.N = NC; g.zc = 3; g.compact = 1;
        g.C = d_C2; g.ldc = NC; g.Cz = (long long)16 * GS;
        g.bias = b2; g.biasz = 4096; g.biasCompact = 1;
        gemm_stage<128>(g, As, Bs);
    }
    { // E = emb @ W1ih[1][:, :512]^T
        GP g = {};
        g.A = emb; g.lda = 512;
        g.B = W1ih + (long long)4096 * 1024; g.ldb = 1024;
        g.K = 512; g.M = 390; g.N = NC; g.zc = 1; g.compact = 1;
        g.C = d_E; g.ldc = NC;
        gemm_stage<128>(g, As, Bs);
    }
    gsync();

    // ---- time loop ----
    for (int t = 0; t < TT; t++) {
        int ptr = t >> 4;
        if ((t & 15) == 0) {
            reset_stage(d_hid + (long long)ptr * BH);
            gsync();
        }

        { // g = A1[.,ptr] + h1 @ W1hh^T        (144 tiles = 1 wave)
            GP g = {};
            g.A = d_h1; g.lda = 1024; g.Az = BH;
            g.B = W1hh; g.ldb = 1024; g.Bz = (long long)4096 * 1024;
            g.K = 1024; g.M = BB; g.N = NC; g.zc = 3; g.compact = 1;
            g.C = d_g; g.ldc = NC; g.Cz = GS;
            g.add0 = d_A1 + (long long)ptr * GS; g.add0z = (long long)16 * GS;
            gemm_stage<128>(g, As, Bs);
        }
        gsync();
        gate_stage(d_g, GS, 3, d_h1, BH, d_uold, BH);
        gsync();

        { // s[i] = uold[i] @ ctxWih slice^T    (144 tiles)
            GP g = {};
            g.A = d_uold; g.lda = 1024; g.Az = BH;
            g.B = cWih; g.ldb = NC; g.Bz = 1024;
            g.K = 1024; g.M = BB; g.N = NC; g.zc = 3; g.compact = 1;
            g.C = d_s; g.ldc = NC; g.Cz = GS;
            gemm_stage<128>(g, As, Bs);
        }
        { // gu[i] = E[i][tok] + CU[ptr] + uold[i] @ W1hh[1]^T   (i = 0,1)
            GP g = {};
            g.A = d_uold; g.lda = 1024; g.Az = BH;
            g.B = W1hh + (long long)4096 * 1024; g.ldb = 1024;
            g.K = 1024; g.M = BB; g.N = NC; g.zc = 2; g.compact = 1;
            g.C = d_g; g.ldc = NC; g.Cz = GS;
            g.add0 = d_CU + (long long)ptr * GS; g.add0z = 0;
            g.Eg = d_E; g.Egz = (long long)130 * NC;
            g.tok = tgt + t; g.tokz = 65536; g.tokstride = 256;
            gemm_stage<128>(g, As, Bs);
        }
        gsync();
        gate_stage(d_g, GS, 2, d_unew, BH, (float*)0, 0);
        gsync();

        { // sn[i] = unew[i] @ ctxWih slice^T  (i = 0,1)
            GP g = {};
            g.A = d_unew; g.lda = 1024; g.Az = BH;
            g.B = cWih; g.ldb = NC; g.Bz = 1024;
            g.K = 1024; g.M = BB; g.N = NC; g.zc = 2; g.compact = 1;
            g.C = d_sn; g.ldc = NC; g.Cz = GS;
            gemm_stage<128>(g, As, Bs);
        }
        { // ctx update 0 (shares phase with sn)
            GP g = {};
            g.A = d_ctxs + 2 * (long long)BH; g.lda = 1024;
            g.B = cWhh; g.ldb = 1024;
            g.K = 1024; g.M = BB; g.N = NC; g.zc = 1; g.compact = 1;
            g.C = d_g; g.ldc = NC;
            g.add0 = d_s; g.add0z = 0;
            g.add1 = d_s + GS; g.add2 = d_s + 2 * (long long)GS;
            g.bias = cb; g.biasCompact = 1;
            gemm_stage<64>(g, As, Bs);
        }
        gsync();
        gate_stage(d_g, 0, 1, d_ctxs, 0, (float*)0, 0);
        gsync();

        { // ctx update 1
            GP g = {};
            g.A = d_ctxs; g.lda = 1024;
            g.B = cWhh; g.ldb = 1024;
            g.K = 1024; g.M = BB; g.N = NC; g.zc = 1; g.compact = 1;
            g.C = d_g; g.ldc = NC;
            g.add0 = d_sn; g.add0z = 0;
            g.add1 = d_s + GS; g.add2 = d_s + 2 * (long long)GS;
            g.bias = cb; g.biasCompact = 1;
            gemm_stage<64>(g, As, Bs);
        }
        gsync();
        gate_stage(d_g, 0, 1, d_ctxs + BH, 0, (float*)0, 0);
        gsync();

        { // ctx update 2
            GP g = {};
            g.A = d_ctxs + (long long)BH; g.lda = 1024;
            g.B = cWhh; g.ldb = 1024;
            g.K = 1024; g.M = BB; g.N = NC; g.zc = 1; g.compact = 1;
            g.C = d_g; g.ldc = NC;
            g.add0 = d_sn; g.add0z = 0;
            g.add1 = d_sn + GS; g.add2 = d_s + 2 * (long long)GS;
            g.bias = cb; g.biasCompact = 1;
            gemm_stage<64>(g, As, Bs);
        }
        gsync();
        gate_stage(d_g, 0, 1, d_ctxs + 2 * (long long)BH, 0, (float*)0, 0);
        gsync();

        { // g2[i] = ctxs[i] @ W2ih[i][:, :1024]^T + h2[i] @ W2hh[i]^T + C2[i][ptr]
            GP g = {};
            g.A = d_ctxs; g.lda = 1024; g.Az = BH;
            g.B = W2ih; g.ldb = 1536; g.Bz = (long long)4096 * 1536;
            g.K = 1024;
            g.A2 = d_h2; g.lda2 = 1024; g.A2z = BH;
            g.B2 = W2hh; g.ldb2 = 1024; g.B2z = (long long)4096 * 1024;
            g.K2 = 1024;
            g.M = BB; g.N = NC; g.zc = 3; g.compact = 1;
            g.C = d_g; g.ldc = NC; g.Cz = GS;
            g.add0 = d_C2 + (long long)ptr * GS; g.add0z = (long long)16 * GS;
            gemm_stage<128>(g, As, Bs);
        }
        gsync();
        gate_stage(d_g, GS, 3, d_h2, BH, (float*)0, 0);
        gsync();

        { // out[i][:,t,:] = (uold[i] + h2[i]) @ outW[i]^T + outb[i]
            GP g = {};
            g.A = d_uold; g.lda = 1024; g.Az = BH;
            g.B = outW; g.ldb = 1024; g.Bz = (long long)130 * 1024;
            g.K = 1024;
            g.A2 = d_h2; g.lda2 = 1024; g.A2z = BH;
            g.B2 = outW; g.ldb2 = 1024; g.B2z = (long long)130 * 1024;
            g.K2 = 1024;
            g.M = BB; g.N = VV; g.zc = 3;
            g.C = out + (long long)t * VV; g.ldc = (long long)TT * VV;
            g.Cz = (long long)BB * TT * VV;
            g.bias = outb; g.biasz = VV;
            gemm_stage<64>(g, As, Bs);
        }
        gsync();   // protects uold/h2 (read by OUT) from next step's writers
    }
}

// ---------------- host ----------------
extern "C" void kernel_launch(void* const* d_in, const int* in_sizes, int n_in,
                              void* d_out, int out_size)
{
    (void)in_sizes; (void)n_in; (void)out_size;
    mega_kernel<<<NBLK, NTHR>>>(
        (const float*)d_in[0],  (const float*)d_in[1],  (const float*)d_in[2],
        (const float*)d_in[3],  (const float*)d_in[4],  (const float*)d_in[5],
        (const float*)d_in[6],  (const float*)d_in[7],  (const float*)d_in[8],
        (const float*)d_in[9],  (const float*)d_in[10], (const float*)d_in[11],
        (const float*)d_in[12], (const float*)d_in[13], (const float*)d_in[14],
        (const int*)d_in[15],   (float*)d_out);
}

// round 9
// speedup vs baseline: 2.9549x; 2.2877x over previous
#include <cuda_runtime.h>
#include <cuda_bf16.h>
#include <cstdint>

// ---------------- problem constants ----------------
#define NBLK 148
#define NTHR 256
#define BB   256
#define NC   3072            // compact gate width (i, gg, o) -- f gate is dead
#define TT   256
#define VV   130
#define BH   (256*1024)
#define GS   (256*3072)

// ---------------- persistent device scratch (fp32) ----------------
__device__ float d_cT   [16*256*512];
__device__ float d_cPrev[16*256*512];
__device__ float d_hid  [16*256*1024];
__device__ float d_A1   [3*16*256*3072];
__device__ float d_CU   [16*256*3072];
__device__ float d_C2   [3*16*256*3072];
__device__ float d_E    [3*130*3072];
__device__ float d_nb1  [3*3072];
__device__ float d_s    [3*256*3072];
__device__ float d_sn   [2*256*3072];
__device__ float d_g    [3*256*3072];

// ---------------- bf16 split weights (compacted rows) ----------------
__device__ __nv_bfloat16 d_W1hhbh[3*3072*1024], d_W1hhbl[3*3072*1024];
__device__ __nv_bfloat16 d_cWihbh[3072*3072],   d_cWihbl[3072*3072];
__device__ __nv_bfloat16 d_cWhhbh[3072*1024],   d_cWhhbl[3072*1024];
__device__ __nv_bfloat16 d_W2ihbh[3*3072*1024], d_W2ihbl[3*3072*1024];
__device__ __nv_bfloat16 d_W2hhbh[3*3072*1024], d_W2hhbl[3*3072*1024];
__device__ __nv_bfloat16 d_outWbh[3*130*1024],  d_outWbl[3*130*1024];

// ---------------- bf16 split activations (A operands) ----------------
__device__ __nv_bfloat16 d_h1bh [3*BH], d_h1bl [3*BH];
__device__ __nv_bfloat16 d_h2bh [3*BH], d_h2bl [3*BH];
__device__ __nv_bfloat16 d_ctxbh[3*BH], d_ctxbl[3*BH];
__device__ __nv_bfloat16 d_uobh [3*BH], d_uobl [3*BH];
__device__ __nv_bfloat16 d_unbh [2*BH], d_unbl [2*BH];

// ---------------- grid barrier (replay-safe, sense via generation) ----------
__device__ unsigned int g_arrive;
__device__ unsigned int g_gen;

__device__ __forceinline__ void gsync()
{
    __threadfence();
    __syncthreads();
    if (threadIdx.x == 0) {
        volatile unsigned int* vg = &g_gen;
        unsigned int g = *vg;
        if (atomicAdd(&g_arrive, 1u) == (unsigned)(gridDim.x - 1)) {
            g_arrive = 0;
            __threadfence();
            *vg = g + 1u;
        } else {
            while (*vg == g) __nanosleep(32);
        }
        __threadfence();
    }
    __syncthreads();
}

// ---------------- f32x2 helpers (preamble FFMA2 path) ----------------
__device__ __forceinline__ void fma2(unsigned long long &c, unsigned long long a,
                                     unsigned long long b) {
    asm("fma.rn.f32x2 %0, %1, %2, %0;" : "+l"(c) : "l"(a), "l"(b));
}
__device__ __forceinline__ unsigned long long dup2(float a) {
    unsigned long long r;
    asm("mov.b64 %0, {%1, %1};" : "=l"(r) : "f"(a));
    return r;
}
__device__ __forceinline__ void unpack2(unsigned long long v, float &lo, float &hi) {
    asm("mov.b64 {%0, %1}, %2;" : "=f"(lo), "=f"(hi) : "l"(v));
}

// ---------------- mma helpers ----------------
__device__ __forceinline__ void ldsm4(unsigned* d, unsigned addr) {
    asm volatile("ldmatrix.sync.aligned.m8n8.x4.shared.b16 {%0,%1,%2,%3},[%4];"
                 : "=r"(d[0]), "=r"(d[1]), "=r"(d[2]), "=r"(d[3]) : "r"(addr));
}
__device__ __forceinline__ void mma16816(float* d, const unsigned* a, const unsigned* b) {
    asm volatile("mma.sync.aligned.m16n8k16.row.col.f32.bf16.bf16.f32 "
                 "{%0,%1,%2,%3},{%4,%5,%6,%7},{%8,%9},{%0,%1,%2,%3};"
                 : "+f"(d[0]), "+f"(d[1]), "+f"(d[2]), "+f"(d[3])
                 : "r"(a[0]), "r"(a[1]), "r"(a[2]), "r"(a[3]), "r"(b[0]), "r"(b[1]));
}

// ================= preamble FFMA2 GEMM =================
struct GP {
    const float* A;  long long lda,  Az;
    const float* B;  long long ldb,  Bz;
    int K, M, N, zc, compact, epi;
    float* C; long long ldc, Cz;
    const float* bias; long long biasz; int biasCompact;
};

__device__ __forceinline__ void run_mm(const float* A, long long lda, int M, int m0,
                                       const float* Bb, long long ldb, int N, int n0, int K,
                                       float* As, float* Bs,
                                       unsigned long long (*acc)[4],
                                       int tid, int tx, int ty)
{
    float4 ra[2], rb[2];
    int nIter = K >> 4;
    for (int it = 0; it < nIter; it++) {
        int k0 = it << 4;
#pragma unroll
        for (int i = 0; i < 2; i++) {
            int j = tid + 256 * i, row = j >> 2, kq = (j & 3) << 2;
            ra[i] = (m0 + row < M)
                ? *(const float4*)(A + (long long)(m0 + row) * lda + k0 + kq)
                : make_float4(0.f, 0.f, 0.f, 0.f);
            rb[i] = (n0 + row < N)
                ? *(const float4*)(Bb + (long long)row * ldb + k0 + kq)
                : make_float4(0.f, 0.f, 0.f, 0.f);
        }
        __syncthreads();
#pragma unroll
        for (int i = 0; i < 2; i++) {
            int j = tid + 256 * i, row = j >> 2, kq = (j & 3) << 2;
            As[(kq + 0) * 128 + row] = ra[i].x;
            As[(kq + 1) * 128 + row] = ra[i].y;
            As[(kq + 2) * 128 + row] = ra[i].z;
            As[(kq + 3) * 128 + row] = ra[i].w;
            Bs[(kq + 0) * 128 + row] = rb[i].x;
            Bs[(kq + 1) * 128 + row] = rb[i].y;
            Bs[(kq + 2) * 128 + row] = rb[i].z;
            Bs[(kq + 3) * 128 + row] = rb[i].w;
        }
        __syncthreads();
#pragma unroll
        for (int kk = 0; kk < 16; kk++) {
            ulonglong2 b01 = *(const ulonglong2*)&Bs[kk * 128 + tx * 8];
            ulonglong2 b23 = *(const ulonglong2*)&Bs[kk * 128 + tx * 8 + 4];
            float av[8];
#pragma unroll
            for (int p = 0; p < 2; p++) {
                ulonglong2 ap = *(const ulonglong2*)&As[kk * 128 + ty * 8 + 4 * p];
                unpack2(ap.x, av[4 * p + 0], av[4 * p + 1]);
                unpack2(ap.y, av[4 * p + 2], av[4 * p + 3]);
            }
#pragma unroll
            for (int mi = 0; mi < 8; mi++) {
                unsigned long long a2 = dup2(av[mi]);
                fma2(acc[mi][0], b01.x, a2);
                fma2(acc[mi][1], b01.y, a2);
                fma2(acc[mi][2], b23.x, a2);
                fma2(acc[mi][3], b23.y, a2);
            }
        }
        __syncthreads();
    }
}

__device__ void gemm_stage(const GP& g, float* As, float* Bs)
{
    int mT = (g.M + 127) >> 7;
    int nT = (g.N + 127) >> 7;
    int total = g.zc * mT * nT;
    int tid = threadIdx.x;
    int tx = tid & 15, ty = tid >> 4;

    for (int tile = blockIdx.x; tile < total; tile += gridDim.x) {
        int z  = tile / (mT * nT);
        int r  = tile - z * (mT * nT);
        int m0 = (r / nT) << 7;
        int n0 = (r % nT) << 7;
        int noff = (g.compact && n0 >= 1024) ? 1024 : 0;

        unsigned long long acc[8][4];
#pragma unroll
        for (int i = 0; i < 8; i++)
#pragma unroll
            for (int j = 0; j < 4; j++) acc[i][j] = 0ull;

        const float* A  = g.A + (long long)z * g.Az;
        const float* Bb = g.B + (long long)z * g.Bz + (long long)(n0 + noff) * g.ldb;
        run_mm(A, g.lda, g.M, m0, Bb, g.ldb, g.N, n0, g.K, As, Bs, acc, tid, tx, ty);

        float* C = g.C + (long long)z * g.Cz;
#pragma unroll
        for (int mi = 0; mi < 8; mi++) {
            int m = m0 + ty * 8 + mi;
            if (m >= g.M) continue;
            float cv[8];
#pragma unroll
            for (int jj = 0; jj < 4; jj++)
                unpack2(acc[mi][jj], cv[2 * jj], cv[2 * jj + 1]);
#pragma unroll
            for (int nj = 0; nj < 8; nj++) {
                int n = n0 + tx * 8 + nj;
                if (n >= g.N) continue;
                float v = cv[nj];
                if (g.bias) v += g.bias[(long long)z * g.biasz + (g.biasCompact ? (n + noff) : n)];
                if (g.epi == 1) v = tanhf(v);
                C[(long long)m * g.ldc + n] = v;
            }
        }
    }
}

// ================= tensor-core GEMM (time loop) =================
struct MGP {
    const __nv_bfloat16 *Ah, *Al;  long long lda,  Az;
    const __nv_bfloat16 *Bh, *Bl;  long long ldb,  Bz;
    const __nv_bfloat16 *A2h, *A2l; long long lda2, A2z;
    const __nv_bfloat16 *B2h, *B2l; long long ldb2, B2z;
    int K, K2, M, N, zc;
    float* C; long long ldc, Cz;
    const float* add0; long long add0z;
    const float *add1, *add2;
    const float* bias; long long biasz; int biasCompact;
    const float* Eg;  long long Egz;
    const int*  tok;  long long tokz;  int tokstride;
};

// smem byte layout: Ahi @0, Alo @6144, Bhi @12288, Blo @18432.
// rows padded to 48 B (24 bf16) -> ldmatrix conflict-free.
// NOTE: Bh/Bl passed as GEMM-BASE pointers; n0 applied exactly once inside.
template<int TM>
__device__ __forceinline__ void mma_run(
    const __nv_bfloat16* Ah, const __nv_bfloat16* Al, long long lda, int M, int m0,
    const __nv_bfloat16* Bh, const __nv_bfloat16* Bl, long long ldb, int N, int n0,
    int K, float* d, char* sm, unsigned sb, int tid, int wm, int wn, int L)
{
    constexpr int NT = (TM == 128) ? 8 : 4;
    constexpr int NW = NT * 8;
    const uint4 z4 = make_uint4(0u, 0u, 0u, 0u);
    int arow = tid >> 1, half = tid & 1;
    bool aact = (tid < TM * 2) && (m0 + arow < M);
    bool bact = (n0 + arow) < N;
    const char* pAh = (const char*)(Ah + (long long)(m0 + arow) * lda + half * 8);
    const char* pAl = (const char*)(Al + (long long)(m0 + arow) * lda + half * 8);
    const char* pBh = (const char*)(Bh + (long long)(n0 + arow) * ldb + half * 8);
    const char* pBl = (const char*)(Bl + (long long)(n0 + arow) * ldb + half * 8);
    int so = arow * 48 + half * 16;
    unsigned aoff = sb + (unsigned)((wm * 32 + (L & 15)) * 48 + (L >> 4) * 16);
    unsigned boff = sb + 12288u +
        (unsigned)((wn * NW + (L & 7) + ((L & 16) ? 8 : 0)) * 48 + ((L & 8) ? 16 : 0));

    uint4 rah = aact ? *(const uint4*)(pAh) : z4;
    uint4 ral = aact ? *(const uint4*)(pAl) : z4;
    uint4 rbh = bact ? *(const uint4*)(pBh) : z4;
    uint4 rbl = bact ? *(const uint4*)(pBl) : z4;

    int nIter = K >> 4;
    for (int it = 1; it <= nIter; it++) {
        if (tid < TM * 2) {
            *(uint4*)(sm + so)        = rah;
            *(uint4*)(sm + 6144 + so) = ral;
        }
        *(uint4*)(sm + 12288 + so) = rbh;
        *(uint4*)(sm + 18432 + so) = rbl;
        __syncthreads();
        if (it < nIter) {   // prefetch next 16-k slice (32 B per row-slice)
            rah = aact ? *(const uint4*)(pAh + it * 32) : z4;
            ral = aact ? *(const uint4*)(pAl + it * 32) : z4;
            rbh = bact ? *(const uint4*)(pBh + it * 32) : z4;
            rbl = bact ? *(const uint4*)(pBl + it * 32) : z4;
        }
        unsigned ah2[2][4], al2[2][4], bh[NT][2], bl[NT][2];
        ldsm4(ah2[0], aoff);
        ldsm4(ah2[1], aoff + 768);
        ldsm4(al2[0], aoff + 6144);
        ldsm4(al2[1], aoff + 6144 + 768);
#pragma unroll
        for (int p = 0; p < NT / 2; p++) {
            unsigned t[4];
            ldsm4(t, boff + p * 768);
            bh[2 * p][0] = t[0]; bh[2 * p][1] = t[1];
            bh[2 * p + 1][0] = t[2]; bh[2 * p + 1][1] = t[3];
            ldsm4(t, boff + 6144 + p * 768);
            bl[2 * p][0] = t[0]; bl[2 * p][1] = t[1];
            bl[2 * p + 1][0] = t[2]; bl[2 * p + 1][1] = t[3];
        }
#pragma unroll
        for (int mt = 0; mt < 2; mt++)
#pragma unroll
            for (int nt = 0; nt < NT; nt++) {
                float* dd = d + (mt * NT + nt) * 4;
                mma16816(dd, ah2[mt], bh[nt]);
                mma16816(dd, ah2[mt], bl[nt]);
                mma16816(dd, al2[mt], bh[nt]);
            }
        __syncthreads();
    }
}

template<int TM>
__device__ void mma_stage(const MGP& g, char* sm, unsigned sb)
{
    constexpr int NT = (TM == 128) ? 8 : 4;
    constexpr int NW = NT * 8;
    int mT = (g.M + TM - 1) / TM;
    int nT = (g.N + 127) >> 7;
    int total = g.zc * mT * nT;
    int tid = threadIdx.x, w = tid >> 5, L = tid & 31;
    int wm = (TM == 128) ? (w >> 1) : (w >> 2);
    int wn = (TM == 128) ? (w & 1) : (w & 3);

    for (int tile = blockIdx.x; tile < total; tile += gridDim.x) {
        int z  = tile / (mT * nT);
        int r  = tile - z * (mT * nT);
        int m0 = (r / nT) * TM;
        int n0 = (r % nT) << 7;

        float d[2 * NT * 4];
#pragma unroll
        for (int i = 0; i < 2 * NT * 4; i++) d[i] = 0.f;

        // FIX (R8 bug): pass B base WITHOUT n0*ldb; mma_run applies n0 once.
        mma_run<TM>(g.Ah + (long long)z * g.Az, g.Al + (long long)z * g.Az, g.lda, g.M, m0,
                    g.Bh + (long long)z * g.Bz,
                    g.Bl + (long long)z * g.Bz, g.ldb, g.N, n0,
                    g.K, d, sm, sb, tid, wm, wn, L);
        if (g.A2h)
            mma_run<TM>(g.A2h + (long long)z * g.A2z, g.A2l + (long long)z * g.A2z,
                        g.lda2, g.M, m0,
                        g.B2h + (long long)z * g.B2z,
                        g.B2l + (long long)z * g.B2z,
                        g.ldb2, g.N, n0, g.K2, d, sm, sb, tid, wm, wn, L);

        float* C = g.C + (long long)z * g.Cz;
#pragma unroll
        for (int mt = 0; mt < 2; mt++) {
            int rbase = m0 + wm * 32 + mt * 16 + (L >> 2);
            int tk0 = 0, tk1 = 0;
            if (g.Eg) {
                tk0 = g.tok[(long long)z * g.tokz + (long long)rbase * g.tokstride];
                tk1 = g.tok[(long long)z * g.tokz + (long long)(rbase + 8) * g.tokstride];
            }
#pragma unroll
            for (int nt = 0; nt < NT; nt++) {
                const float* dd = d + (mt * NT + nt) * 4;
                int cbase = n0 + wn * NW + nt * 8 + (L & 3) * 2;
#pragma unroll
                for (int e = 0; e < 4; e++) {
                    int m = rbase + (e >= 2 ? 8 : 0);
                    int n = cbase + (e & 1);
                    if (n >= g.N || m >= g.M) continue;
                    float v = dd[e];
                    if (g.add0) v += g.add0[(long long)z * g.add0z + (long long)m * g.N + n];
                    if (g.add1) v += g.add1[(long long)m * g.N + n];
                    if (g.add2) v += g.add2[(long long)m * g.N + n];
                    if (g.bias) {
                        int nf = g.biasCompact ? (n + (n >= 1024 ? 1024 : 0)) : n;
                        v += g.bias[(long long)z * g.biasz + nf];
                    }
                    if (g.Eg)
                        v += g.Eg[(long long)z * g.Egz +
                                  (long long)(e >= 2 ? tk1 : tk0) * g.N + n];
                    C[(long long)m * g.ldc + n] = v;
                }
            }
        }
    }
}

// ---------------- elementwise stages ----------------
__device__ __forceinline__ void split_bf16(float v, __nv_bfloat16& h, __nv_bfloat16& l)
{
    h = __float2bfloat16(v);
    l = __float2bfloat16(v - __bfloat162float(h));
}

// gate: h = sigmoid(o) * tanh(sigmoid(i) * tanh(gg)); writes bf16 hi/lo state(s)
__device__ void gate_stage(const float* gsrc, long long gz, int zc,
                           __nv_bfloat16* d0h, __nv_bfloat16* d0l, long long d0z,
                           __nv_bfloat16* d1h, __nv_bfloat16* d1l, long long d1z)
{
    int total = zc << 18;
    for (int idx = blockIdx.x * NTHR + threadIdx.x; idx < total; idx += gridDim.x * NTHR) {
        int z   = idx >> 18;
        int rem = idx & ((1 << 18) - 1);
        int m = rem >> 10, j = rem & 1023;
        const float* gp = gsrc + (long long)z * gz + (long long)m * NC;
        float gi = gp[j], gg = gp[1024 + j], go = gp[2048 + j];
        float si = 1.f / (1.f + expf(-gi));
        float so = 1.f / (1.f + expf(-go));
        float v  = so * tanhf(si * tanhf(gg));
        __nv_bfloat16 bh, bl;
        split_bf16(v, bh, bl);
        long long o = (long long)z * d0z + (long long)m * 1024 + j;
        d0h[o] = bh; d0l[o] = bl;
        if (d1h) {
            long long o1 = (long long)z * d1z + (long long)m * 1024 + j;
            d1h[o1] = bh; d1l[o1] = bl;
        }
    }
}

__device__ void reset_stage(const float* hid)
{
    for (int idx = blockIdx.x * NTHR + threadIdx.x; idx < (1 << 18);
         idx += gridDim.x * NTHR) {
        float v = hid[idx];
        __nv_bfloat16 bh, bl;
        split_bf16(v, bh, bl);
#pragma unroll
        for (int z = 0; z < 3; z++) {
            d_h1bh[z * BH + idx] = bh; d_h1bl[z * BH + idx] = bl;
            d_h2bh[z * BH + idx] = bh; d_h2bl[z * BH + idx] = bl;
        }
        d_ctxbh[2 * BH + idx] = bh; d_ctxbl[2 * BH + idx] = bl;
    }
}

__device__ void prep_stage(const float* c)
{
    for (int idx = blockIdx.x * NTHR + threadIdx.x; idx < (16 * 256 * 512);
         idx += gridDim.x * NTHR) {
        int ptr = idx >> 17;
        int rem = idx & 131071;
        int b = rem >> 9, k = rem & 511;
        d_cT[idx] = c[((b << 4) + ptr) * 512 + k];
        int pm = ptr > 0 ? ptr - 1 : 0;
        d_cPrev[idx] = c[((b << 4) + pm) * 512 + k];
    }
}

__device__ void nb1_stage(const float* emb, const float* W1ih, const float* b1)
{
    for (int idx = blockIdx.x * NTHR + threadIdx.x; idx < 3 * 3072;
         idx += gridDim.x * NTHR) {
        int i = idx / 3072, n = idx - (idx / 3072) * 3072;
        int nfull = n + (n >= 1024 ? 1024 : 0);
        const float* e = emb + (long long)i * 130 * 512;            // v = 0 row
        const float* w = W1ih + ((long long)i * 4096 + nfull) * 1024;
        float s = b1[i * 4096 + nfull];
        for (int k = 0; k < 512; k++) s += e[k] * w[k];
        d_nb1[idx] = s;
    }
}

// weight -> compacted bf16 hi/lo
__device__ void convw_stage(const float* src, long long sld, long long sz,
                            int zc, int rows, int K, int compact,
                            __nv_bfloat16* h, __nv_bfloat16* l)
{
    int total = zc * rows * K;
    for (int idx = blockIdx.x * NTHR + threadIdx.x; idx < total;
         idx += gridDim.x * NTHR) {
        int k = idx % K;
        int rz = idx / K;
        int r = rz % rows;
        int z = rz / rows;
        int rf = compact ? (r + (r >= 1024 ? 1024 : 0)) : r;
        float v = src[(long long)z * sz + (long long)rf * sld + k];
        __nv_bfloat16 bh, bl;
        split_bf16(v, bh, bl);
        h[idx] = bh; l[idx] = bl;
    }
}

// ---------------- the single persistent kernel ----------------
__global__ void __launch_bounds__(NTHR, 1)
mega_kernel(const float* c, const float* W1ih, const float* W1hh, const float* b1,
            const float* cWih, const float* cWhh, const float* cb,
            const float* W2ih, const float* W2hh, const float* b2,
            const float* outW, const float* outb,
            const float* hidW, const float* hidb,
            const float* emb, const int* tgt, float* out)
{
    __shared__ __align__(16) float smem_f[8192];   // 32 KB, shared by both paths
    float* As = smem_f;
    float* Bs = smem_f + 4096;
    char* sm = (char*)smem_f;
    unsigned sb;
    asm("{.reg .u64 t; cvta.to.shared.u64 t, %1; cvt.u32.u64 %0, t;}"
        : "=r"(sb) : "l"(smem_f));

    // ---- phase 0: transpose + notes0 hoist + weight conversion ----
    prep_stage(c);
    nb1_stage(emb, W1ih, b1);
    convw_stage(W1hh, 1024, 4096LL * 1024, 3, 3072, 1024, 1, d_W1hhbh, d_W1hhbl);
    convw_stage(cWih, 3072, 0,             1, 3072, 3072, 1, d_cWihbh, d_cWihbl);
    convw_stage(cWhh, 1024, 0,             1, 3072, 1024, 1, d_cWhhbh, d_cWhhbl);
    convw_stage(W2ih, 1536, 4096LL * 1536, 3, 3072, 1024, 1, d_W2ihbh, d_W2ihbl);
    convw_stage(W2hh, 1024, 4096LL * 1024, 3, 3072, 1024, 1, d_W2hhbh, d_W2hhbl);
    convw_stage(outW, 1024, 130LL * 1024,  3, 130,  1024, 0, d_outWbh, d_outWbl);
    gsync();

    // ---- phase 1: per-bar hoisted GEMMs (FFMA2 path) ----
    { // hidden[ptr] = tanh(cPrev @ hidW^T + hidb)
        GP g = {};
        g.A = d_cPrev; g.lda = 512; g.B = hidW; g.ldb = 512;
        g.K = 512; g.M = 4096; g.N = 1024; g.zc = 1; g.epi = 1;
        g.C = d_hid; g.ldc = 1024;
        g.bias = hidb;
        gemm_stage(g, As, Bs);
    }
    { // A1[i][ptr] = nb1[i] + cT @ W1ih[i][:,512:]^T
        GP g = {};
        g.A = d_cT; g.lda = 512;
        g.B = W1ih + 512; g.ldb = 1024; g.Bz = 4096LL * 1024;
        g.K = 512; g.M = 4096; g.N = NC; g.zc = 3; g.compact = 1;
        g.C = d_A1; g.ldc = NC; g.Cz = 16LL * GS;
        g.bias = d_nb1; g.biasz = NC;
        gemm_stage(g, As, Bs);
    }
    { // CU[ptr] = cT @ W1ih[1][:,512:]^T + b1[1]
        GP g = {};
        g.A = d_cT; g.lda = 512;
        g.B = W1ih + 4096LL * 1024 + 512; g.ldb = 1024;
        g.K = 512; g.M = 4096; g.N = NC; g.zc = 1; g.compact = 1;
        g.C = d_CU; g.ldc = NC;
        g.bias = b1 + 4096; g.biasCompact = 1;
        gemm_stage(g, As, Bs);
    }
    { // C2[i][ptr] = cT @ W2ih[i][:,1024:]^T + b2[i]
        GP g = {};
        g.A = d_cT; g.lda = 512;
        g.B = W2ih + 1024; g.ldb = 1536; g.Bz = 4096LL * 1536;
        g.K = 512; g.M = 4096; g.N = NC; g.zc = 3; g.compact = 1;
        g.C = d_C2; g.ldc = NC; g.Cz = 16LL * GS;
        g.bias = b2; g.biasz = 4096; g.biasCompact = 1;
        gemm_stage(g, As, Bs);
    }
    { // E = emb @ W1ih[1][:, :512]^T
        GP g = {};
        g.A = emb; g.lda = 512;
        g.B = W1ih + 4096LL * 1024; g.ldb = 1024;
        g.K = 512; g.M = 390; g.N = NC; g.zc = 1; g.compact = 1;
        g.C = d_E; g.ldc = NC;
        gemm_stage(g, As, Bs);
    }
    gsync();

    // ---- time loop (tensor-core path) ----
    for (int t = 0; t < TT; t++) {
        int ptr = t >> 4;
        if ((t & 15) == 0) {
            reset_stage(d_hid + (long long)ptr * BH);
            gsync();
        }

        { // g = A1[.,ptr] + h1 @ W1hh^T
            MGP g = {};
            g.Ah = d_h1bh; g.Al = d_h1bl; g.lda = 1024; g.Az = BH;
            g.Bh = d_W1hhbh; g.Bl = d_W1hhbl; g.ldb = 1024; g.Bz = 3072LL * 1024;
            g.K = 1024; g.M = BB; g.N = NC; g.zc = 3;
            g.C = d_g; g.ldc = NC; g.Cz = GS;
            g.add0 = d_A1 + (long long)ptr * GS; g.add0z = 16LL * GS;
            mma_stage<128>(g, sm, sb);
        }
        gsync();
        gate_stage(d_g, GS, 3, d_h1bh, d_h1bl, BH, d_uobh, d_uobl, BH);
        gsync();

        { // s[i] = uold[i] @ cWih[:, i*1024:]^T
            MGP g = {};
            g.Ah = d_uobh; g.Al = d_uobl; g.lda = 1024; g.Az = BH;
            g.Bh = d_cWihbh; g.Bl = d_cWihbl; g.ldb = 3072; g.Bz = 1024;
            g.K = 1024; g.M = BB; g.N = NC; g.zc = 3;
            g.C = d_s; g.ldc = NC; g.Cz = GS;
            mma_stage<128>(g, sm, sb);
        }
        { // gu[i] = E[i][tok] + CU[ptr] + uold[i] @ W1hh[1]^T   (i = 0,1)
            MGP g = {};
            g.Ah = d_uobh; g.Al = d_uobl; g.lda = 1024; g.Az = BH;
            g.Bh = d_W1hhbh + 3072LL * 1024; g.Bl = d_W1hhbl + 3072LL * 1024;
            g.ldb = 1024; g.Bz = 0;
            g.K = 1024; g.M = BB; g.N = NC; g.zc = 2;
            g.C = d_g; g.ldc = NC; g.Cz = GS;
            g.add0 = d_CU + (long long)ptr * GS; g.add0z = 0;
            g.Eg = d_E; g.Egz = 130LL * NC;
            g.tok = tgt + t; g.tokz = 65536; g.tokstride = 256;
            mma_stage<128>(g, sm, sb);
        }
        gsync();
        gate_stage(d_g, GS, 2, d_unbh, d_unbl, BH, (__nv_bfloat16*)0, (__nv_bfloat16*)0, 0);
        gsync();

        { // sn[i] = unew[i] @ cWih[:, i*1024:]^T  (i = 0,1)
            MGP g = {};
            g.Ah = d_unbh; g.Al = d_unbl; g.lda = 1024; g.Az = BH;
            g.Bh = d_cWihbh; g.Bl = d_cWihbl; g.ldb = 3072; g.Bz = 1024;
            g.K = 1024; g.M = BB; g.N = NC; g.zc = 2;
            g.C = d_sn; g.ldc = NC; g.Cz = GS;
            mma_stage<128>(g, sm, sb);
        }
        { // ctx update 0 (shares phase with sn)
            MGP g = {};
            g.Ah = d_ctxbh + 2LL * BH; g.Al = d_ctxbl + 2LL * BH; g.lda = 1024; g.Az = 0;
            g.Bh = d_cWhhbh; g.Bl = d_cWhhbl; g.ldb = 1024; g.Bz = 0;
            g.K = 1024; g.M = BB; g.N = NC; g.zc = 1;
            g.C = d_g; g.ldc = NC; g.Cz = 0;
            g.add0 = d_s; g.add0z = 0;
            g.add1 = d_s + GS; g.add2 = d_s + 2LL * GS;
            g.bias = cb; g.biasz = 0; g.biasCompact = 1;
            mma_stage<64>(g, sm, sb);
        }
        gsync();
        gate_stage(d_g, 0, 1, d_ctxbh, d_ctxbl, 0, (__nv_bfloat16*)0, (__nv_bfloat16*)0, 0);
        gsync();

        { // ctx update 1
            MGP g = {};
            g.Ah = d_ctxbh; g.Al = d_ctxbl; g.lda = 1024; g.Az = 0;
            g.Bh = d_cWhhbh; g.Bl = d_cWhhbl; g.ldb = 1024; g.Bz = 0;
            g.K = 1024; g.M = BB; g.N = NC; g.zc = 1;
            g.C = d_g; g.ldc = NC; g.Cz = 0;
            g.add0 = d_sn; g.add0z = 0;
            g.add1 = d_s + GS; g.add2 = d_s + 2LL * GS;
            g.bias = cb; g.biasz = 0; g.biasCompact = 1;
            mma_stage<64>(g, sm, sb);
        }
        gsync();
        gate_stage(d_g, 0, 1, d_ctxbh + BH, d_ctxbl + BH, 0,
                   (__nv_bfloat16*)0, (__nv_bfloat16*)0, 0);
        gsync();

        { // ctx update 2
            MGP g = {};
            g.Ah = d_ctxbh + (long long)BH; g.Al = d_ctxbl + (long long)BH;
            g.lda = 1024; g.Az = 0;
            g.Bh = d_cWhhbh; g.Bl = d_cWhhbl; g.ldb = 1024; g.Bz = 0;
            g.K = 1024; g.M = BB; g.N = NC; g.zc = 1;
            g.C = d_g; g.ldc = NC; g.Cz = 0;
            g.add0 = d_sn; g.add0z = 0;
            g.add1 = d_sn + GS; g.add2 = d_s + 2LL * GS;
            g.bias = cb; g.biasz = 0; g.biasCompact = 1;
            mma_stage<64>(g, sm, sb);
        }
        gsync();
        gate_stage(d_g, 0, 1, d_ctxbh + 2LL * BH, d_ctxbl + 2LL * BH, 0,
                   (__nv_bfloat16*)0, (__nv_bfloat16*)0, 0);
        gsync();

        { // g2[i] = ctx[i] @ W2ih[i][:, :1024]^T + h2[i] @ W2hh[i]^T + C2[i][ptr]
            MGP g = {};
            g.Ah = d_ctxbh; g.Al = d_ctxbl; g.lda = 1024; g.Az = BH;
            g.Bh = d_W2ihbh; g.Bl = d_W2ihbl; g.ldb = 1024; g.Bz = 3072LL * 1024;
            g.A2h = d_h2bh; g.A2l = d_h2bl; g.lda2 = 1024; g.A2z = BH;
            g.B2h = d_W2hhbh; g.B2l = d_W2hhbl; g.ldb2 = 1024; g.B2z = 3072LL * 1024;
            g.K = 1024; g.K2 = 1024; g.M = BB; g.N = NC; g.zc = 3;
            g.C = d_g; g.ldc = NC; g.Cz = GS;
            g.add0 = d_C2 + (long long)ptr * GS; g.add0z = 16LL * GS;
            mma_stage<128>(g, sm, sb);
        }
        gsync();
        gate_stage(d_g, GS, 3, d_h2bh, d_h2bl, BH, (__nv_bfloat16*)0, (__nv_bfloat16*)0, 0);
        gsync();

        { // out[i][:,t,:] = (uold[i] + h2[i]) @ outW[i]^T + outb[i]
            MGP g = {};
            g.Ah = d_uobh; g.Al = d_uobl; g.lda = 1024; g.Az = BH;
            g.Bh = d_outWbh; g.Bl = d_outWbl; g.ldb = 1024; g.Bz = 130LL * 1024;
            g.A2h = d_h2bh; g.A2l = d_h2bl; g.lda2 = 1024; g.A2z = BH;
            g.B2h = d_outWbh; g.B2l = d_outWbl; g.ldb2 = 1024; g.B2z = 130LL * 1024;
            g.K = 1024; g.K2 = 1024; g.M = BB; g.N = VV; g.zc = 3;
            g.C = out + (long long)t * VV; g.ldc = (long long)TT * VV;
            g.Cz = (long long)BB * TT * VV;
            g.bias = outb; g.biasz = VV;
            mma_stage<64>(g, sm, sb);
        }
        gsync();   // protects uold/h2 (read by OUT) from next step's writers
    }
}

// ---------------- host ----------------
extern "C" void kernel_launch(void* const* d_in, const int* in_sizes, int n_in,
                              void* d_out, int out_size)
{
    (void)in_sizes; (void)n_in; (void)out_size;
    mega_kernel<<<NBLK, NTHR>>>(
        (const float*)d_in[0],  (const float*)d_in[1],  (const float*)d_in[2],
        (const float*)d_in[3],  (const float*)d_in[4],  (const float*)d_in[5],
        (const float*)d_in[6],  (const float*)d_in[7],  (const float*)d_in[8],
        (const float*)d_in[9],  (const float*)d_in[10], (const float*)d_in[11],
        (const float*)d_in[12], (const float*)d_in[13], (const float*)d_in[14],
        (const int*)d_in[15],   (float*)d_out);
}

// round 10
// speedup vs baseline: 3.4101x; 1.1541x over previous
#include <cuda_runtime.h>
#include <cuda_bf16.h>
#include <cstdint>

// ---------------- problem constants ----------------
#define NBLK 148
#define NTHR 512
#define BB   256
#define NC   3072            // compact gate width (i, gg, o) -- f gate is dead
#define TT   256
#define VV   130
#define BH   (256*1024)
#define GS   (256*3072)

// ---------------- persistent device scratch (fp32) ----------------
__device__ float d_cT   [16*256*512];
__device__ float d_cPrev[16*256*512];
__device__ float d_hid  [16*256*1024];
__device__ float d_A1   [3*16*256*3072];
__device__ float d_CU   [16*256*3072];
__device__ float d_C2   [3*16*256*3072];
__device__ float d_E    [3*130*3072];
__device__ float d_nb1  [3*3072];
__device__ float d_s    [3*256*3072];
__device__ float d_sn   [2*256*3072];
__device__ float d_g    [3*256*3072];

// ---------------- bf16 split weights (compacted rows) ----------------
__device__ __nv_bfloat16 d_W1hhbh[3*3072*1024], d_W1hhbl[3*3072*1024];
__device__ __nv_bfloat16 d_cWihbh[3072*3072],   d_cWihbl[3072*3072];
__device__ __nv_bfloat16 d_cWhhbh[3072*1024],   d_cWhhbl[3072*1024];
__device__ __nv_bfloat16 d_W2ihbh[3*3072*1024], d_W2ihbl[3*3072*1024];
__device__ __nv_bfloat16 d_W2hhbh[3*3072*1024], d_W2hhbl[3*3072*1024];
__device__ __nv_bfloat16 d_outWbh[3*130*1024],  d_outWbl[3*130*1024];

// ---------------- bf16 split activations (A operands) ----------------
__device__ __nv_bfloat16 d_h1bh [3*BH], d_h1bl [3*BH];
__device__ __nv_bfloat16 d_h2bh [3*BH], d_h2bl [3*BH];
__device__ __nv_bfloat16 d_ctxbh[3*BH], d_ctxbl[3*BH];
__device__ __nv_bfloat16 d_uobh [3*BH], d_uobl [3*BH];
__device__ __nv_bfloat16 d_unbh [2*BH], d_unbl [2*BH];

// ---------------- grid barrier (replay-safe, sense via generation) ----------
__device__ unsigned int g_arrive;
__device__ unsigned int g_gen;

__device__ __forceinline__ void gsync()
{
    __threadfence();
    __syncthreads();
    if (threadIdx.x == 0) {
        volatile unsigned int* vg = &g_gen;
        unsigned int g = *vg;
        if (atomicAdd(&g_arrive, 1u) == (unsigned)(gridDim.x - 1)) {
            g_arrive = 0;
            __threadfence();
            *vg = g + 1u;
        } else {
            while (*vg == g) __nanosleep(32);
        }
        __threadfence();
    }
    __syncthreads();
}

// ---------------- f32x2 helpers (preamble FFMA2 path) ----------------
__device__ __forceinline__ void fma2(unsigned long long &c, unsigned long long a,
                                     unsigned long long b) {
    asm("fma.rn.f32x2 %0, %1, %2, %0;" : "+l"(c) : "l"(a), "l"(b));
}
__device__ __forceinline__ void unpack2(unsigned long long v, float &lo, float &hi) {
    asm("mov.b64 {%0, %1}, %2;" : "=f"(lo), "=f"(hi) : "l"(v));
}
__device__ __forceinline__ unsigned long long dup2(float a) {
    unsigned long long r;
    asm("mov.b64 %0, {%1, %1};" : "=l"(r) : "f"(a));
    return r;
}

// ---------------- mma helpers ----------------
__device__ __forceinline__ void ldsm4(unsigned* d, unsigned addr) {
    asm volatile("ldmatrix.sync.aligned.m8n8.x4.shared.b16 {%0,%1,%2,%3},[%4];"
                 : "=r"(d[0]), "=r"(d[1]), "=r"(d[2]), "=r"(d[3]) : "r"(addr));
}
__device__ __forceinline__ void mma16816(float* d, const unsigned* a, const unsigned* b) {
    asm volatile("mma.sync.aligned.m16n8k16.row.col.f32.bf16.bf16.f32 "
                 "{%0,%1,%2,%3},{%4,%5,%6,%7},{%8,%9},{%0,%1,%2,%3};"
                 : "+f"(d[0]), "+f"(d[1]), "+f"(d[2]), "+f"(d[3])
                 : "r"(a[0]), "r"(a[1]), "r"(a[2]), "r"(a[3]), "r"(b[0]), "r"(b[1]));
}

// ================= preamble FFMA2 GEMM (512-thread variant) =================
struct GP {
    const float* A;  long long lda,  Az;
    const float* B;  long long ldb,  Bz;
    int K, M, N, zc, compact, epi;
    float* C; long long ldc, Cz;
    const float* bias; long long biasz; int biasCompact;
};

__device__ __forceinline__ void run_mm(const float* A, long long lda, int M, int m0,
                                       const float* Bb, long long ldb, int N, int n0, int K,
                                       float* As, float* Bs,
                                       unsigned long long (*acc)[4],
                                       int tid, int tx, int ty)
{
    int nIter = K >> 4;
    int row = tid >> 2, kq = (tid & 3) << 2;
    for (int it = 0; it < nIter; it++) {
        int k0 = it << 4;
        float4 ra = (m0 + row < M)
            ? *(const float4*)(A + (long long)(m0 + row) * lda + k0 + kq)
            : make_float4(0.f, 0.f, 0.f, 0.f);
        float4 rb = (n0 + row < N)
            ? *(const float4*)(Bb + (long long)row * ldb + k0 + kq)
            : make_float4(0.f, 0.f, 0.f, 0.f);
        __syncthreads();
        As[(kq + 0) * 128 + row] = ra.x;
        As[(kq + 1) * 128 + row] = ra.y;
        As[(kq + 2) * 128 + row] = ra.z;
        As[(kq + 3) * 128 + row] = ra.w;
        Bs[(kq + 0) * 128 + row] = rb.x;
        Bs[(kq + 1) * 128 + row] = rb.y;
        Bs[(kq + 2) * 128 + row] = rb.z;
        Bs[(kq + 3) * 128 + row] = rb.w;
        __syncthreads();
#pragma unroll
        for (int kk = 0; kk < 16; kk++) {
            ulonglong2 b01 = *(const ulonglong2*)&Bs[kk * 128 + tx * 8];
            ulonglong2 b23 = *(const ulonglong2*)&Bs[kk * 128 + tx * 8 + 4];
            ulonglong2 ap  = *(const ulonglong2*)&As[kk * 128 + ty * 4];
            float av[4];
            unpack2(ap.x, av[0], av[1]);
            unpack2(ap.y, av[2], av[3]);
#pragma unroll
            for (int mi = 0; mi < 4; mi++) {
                unsigned long long a2 = dup2(av[mi]);
                fma2(acc[mi][0], b01.x, a2);
                fma2(acc[mi][1], b01.y, a2);
                fma2(acc[mi][2], b23.x, a2);
                fma2(acc[mi][3], b23.y, a2);
            }
        }
    }
    __syncthreads();
}

__device__ void gemm_stage(const GP& g, float* As, float* Bs)
{
    int mT = (g.M + 127) >> 7;
    int nT = (g.N + 127) >> 7;
    int total = g.zc * mT * nT;
    int tid = threadIdx.x;
    int tx = tid & 15, ty = tid >> 4;   // ty 0..31 (4 rows each), tx 0..15 (8 cols)

    for (int tile = blockIdx.x; tile < total; tile += gridDim.x) {
        int z  = tile / (mT * nT);
        int r  = tile - z * (mT * nT);
        int m0 = (r / nT) << 7;
        int n0 = (r % nT) << 7;
        int noff = (g.compact && n0 >= 1024) ? 1024 : 0;

        unsigned long long acc[4][4];
#pragma unroll
        for (int i = 0; i < 4; i++)
#pragma unroll
            for (int j = 0; j < 4; j++) acc[i][j] = 0ull;

        const float* A  = g.A + (long long)z * g.Az;
        const float* Bb = g.B + (long long)z * g.Bz + (long long)(n0 + noff) * g.ldb;
        run_mm(A, g.lda, g.M, m0, Bb, g.ldb, g.N, n0, g.K, As, Bs, acc, tid, tx, ty);

        float* C = g.C + (long long)z * g.Cz;
#pragma unroll
        for (int mi = 0; mi < 4; mi++) {
            int m = m0 + ty * 4 + mi;
            if (m >= g.M) continue;
            float cv[8];
#pragma unroll
            for (int jj = 0; jj < 4; jj++)
                unpack2(acc[mi][jj], cv[2 * jj], cv[2 * jj + 1]);
#pragma unroll
            for (int nj = 0; nj < 8; nj++) {
                int n = n0 + tx * 8 + nj;
                if (n >= g.N) continue;
                float v = cv[nj];
                if (g.bias) v += g.bias[(long long)z * g.biasz + (g.biasCompact ? (n + noff) : n)];
                if (g.epi == 1) v = tanhf(v);
                C[(long long)m * g.ldc + n] = v;
            }
        }
    }
}

// ================= tensor-core GEMM (time loop) =================
struct MGP {
    const __nv_bfloat16 *Ah, *Al;  long long lda,  Az;
    const __nv_bfloat16 *Bh, *Bl;  long long ldb,  Bz;
    const __nv_bfloat16 *A2h, *A2l; long long lda2, A2z;
    const __nv_bfloat16 *B2h, *B2l; long long ldb2, B2z;
    int K, K2, M, N, zc;
    float* C; long long ldc, Cz;
    const float* add0; long long add0z;
    const float *add1, *add2;
    const float* bias; long long biasz; int biasCompact;
    const float* Eg;  long long Egz;
    const int*  tok;  long long tokz;  int tokstride;
};

// Per-buffer byte layout (stride 24576): Ahi@0, Alo@6144, Bhi@12288, Blo@18432.
// Rows padded to 48 B -> ldmatrix conflict-free. Two buffers: +0 / +24576.
// Threads 0..255 stage A, 256..511 stage B. One __syncthreads per 16-k slice.
template<int TM>
__device__ __forceinline__ void mma_run(
    const __nv_bfloat16* Ah, const __nv_bfloat16* Al, long long lda, int M, int m0,
    const __nv_bfloat16* Bh, const __nv_bfloat16* Bl, long long ldb, int N, int n0,
    int K, float* d, char* sm, unsigned sb, int tid, int wm, int wn, int L)
{
    constexpr int NT = (TM == 128) ? 4 : 2;
    constexpr int NW = NT * 8;
    const uint4 z4 = make_uint4(0u, 0u, 0u, 0u);
    bool isA = tid < 256;
    int st = isA ? tid : tid - 256;
    int row = st >> 1, half = st & 1;
    bool act, sact;
    const char *ph, *pl;
    if (isA) {
        sact = row < TM;
        act  = sact && (m0 + row < M);
        ph = (const char*)(Ah + (long long)(m0 + row) * lda + half * 8);
        pl = (const char*)(Al + (long long)(m0 + row) * lda + half * 8);
    } else {
        sact = true;
        act  = (n0 + row) < N;
        ph = (const char*)(Bh + (long long)(n0 + row) * ldb + half * 8);
        pl = (const char*)(Bl + (long long)(n0 + row) * ldb + half * 8);
    }
    int sob = row * 48 + half * 16 + (isA ? 0 : 12288);
    unsigned aoff = sb + (unsigned)((wm * 32 + (L & 15)) * 48 + (L >> 4) * 16);
    unsigned boff = sb + 12288u +
        (unsigned)((wn * NW + (L & 7) + ((L & 16) ? 8 : 0)) * 48 + ((L & 8) ? 16 : 0));

    int nIter = K >> 4;
    uint4 rh = act ? *(const uint4*)(ph) : z4;
    uint4 rl = act ? *(const uint4*)(pl) : z4;
    if (sact) {                       // slice 0 -> buf0
        *(uint4*)(sm + sob)        = rh;
        *(uint4*)(sm + 6144 + sob) = rl;
    }
    if (1 < nIter) {                  // prefetch slice 1
        rh = act ? *(const uint4*)(ph + 32) : z4;
        rl = act ? *(const uint4*)(pl + 32) : z4;
    }
    __syncthreads();

    for (int it = 0; it < nIter; it++) {
        unsigned bufc = (unsigned)((it & 1) * 24576);
        if (it + 1 < nIter) {         // store prefetched slice it+1 into other buffer
            int bo = ((it + 1) & 1) * 24576 + sob;
            if (sact) {
                *(uint4*)(sm + bo)        = rh;
                *(uint4*)(sm + 6144 + bo) = rl;
            }
            if (it + 2 < nIter) {     // prefetch slice it+2
                rh = act ? *(const uint4*)(ph + (it + 2) * 32) : z4;
                rl = act ? *(const uint4*)(pl + (it + 2) * 32) : z4;
            }
        }
        // compute on buffer `bufc`
        unsigned ah2[2][4], al2[2][4], bh[NT][2], bl[NT][2];
        ldsm4(ah2[0], aoff + bufc);
        ldsm4(ah2[1], aoff + bufc + 768);
        ldsm4(al2[0], aoff + bufc + 6144);
        ldsm4(al2[1], aoff + bufc + 6144 + 768);
#pragma unroll
        for (int p = 0; p < NT / 2; p++) {
            unsigned t[4];
            ldsm4(t, boff + bufc + p * 768);
            bh[2 * p][0] = t[0]; bh[2 * p][1] = t[1];
            bh[2 * p + 1][0] = t[2]; bh[2 * p + 1][1] = t[3];
            ldsm4(t, boff + bufc + 6144 + p * 768);
            bl[2 * p][0] = t[0]; bl[2 * p][1] = t[1];
            bl[2 * p + 1][0] = t[2]; bl[2 * p + 1][1] = t[3];
        }
#pragma unroll
        for (int mt = 0; mt < 2; mt++)
#pragma unroll
            for (int nt = 0; nt < NT; nt++) {
                float* dd = d + (mt * NT + nt) * 4;
                mma16816(dd, ah2[mt], bh[nt]);
                mma16816(dd, ah2[mt], bl[nt]);
                mma16816(dd, al2[mt], bh[nt]);
            }
        __syncthreads();
    }
}

template<int TM>
__device__ void mma_stage(const MGP& g, char* sm, unsigned sb)
{
    constexpr int NT = (TM == 128) ? 4 : 2;
    constexpr int NW = NT * 8;
    int mT = (g.M + TM - 1) / TM;
    int nT = (g.N + 127) >> 7;
    int total = g.zc * mT * nT;
    int tid = threadIdx.x, w = tid >> 5, L = tid & 31;
    int wm = (TM == 128) ? (w >> 2) : (w >> 3);   // 4 / 2 m-warps of 32 rows
    int wn = (TM == 128) ? (w & 3) : (w & 7);     // 4 / 8 n-warps of NW cols

    for (int tile = blockIdx.x; tile < total; tile += gridDim.x) {
        int z  = tile / (mT * nT);
        int r  = tile - z * (mT * nT);
        int m0 = (r / nT) * TM;
        int n0 = (r % nT) << 7;

        float d[2 * NT * 4];
#pragma unroll
        for (int i = 0; i < 2 * NT * 4; i++) d[i] = 0.f;

        mma_run<TM>(g.Ah + (long long)z * g.Az, g.Al + (long long)z * g.Az, g.lda, g.M, m0,
                    g.Bh + (long long)z * g.Bz,
                    g.Bl + (long long)z * g.Bz, g.ldb, g.N, n0,
                    g.K, d, sm, sb, tid, wm, wn, L);
        if (g.A2h)
            mma_run<TM>(g.A2h + (long long)z * g.A2z, g.A2l + (long long)z * g.A2z,
                        g.lda2, g.M, m0,
                        g.B2h + (long long)z * g.B2z,
                        g.B2l + (long long)z * g.B2z,
                        g.ldb2, g.N, n0, g.K2, d, sm, sb, tid, wm, wn, L);

        float* C = g.C + (long long)z * g.Cz;
#pragma unroll
        for (int mt = 0; mt < 2; mt++) {
            int rbase = m0 + wm * 32 + mt * 16 + (L >> 2);
            int tk0 = 0, tk1 = 0;
            if (g.Eg) {
                tk0 = g.tok[(long long)z * g.tokz + (long long)rbase * g.tokstride];
                tk1 = g.tok[(long long)z * g.tokz + (long long)(rbase + 8) * g.tokstride];
            }
#pragma unroll
            for (int nt = 0; nt < NT; nt++) {
                const float* dd = d + (mt * NT + nt) * 4;
                int cbase = n0 + wn * NW + nt * 8 + (L & 3) * 2;
#pragma unroll
                for (int e = 0; e < 4; e++) {
                    int m = rbase + (e >= 2 ? 8 : 0);
                    int n = cbase + (e & 1);
                    if (n >= g.N || m >= g.M) continue;
                    float v = dd[e];
                    if (g.add0) v += g.add0[(long long)z * g.add0z + (long long)m * g.N + n];
                    if (g.add1) v += g.add1[(long long)m * g.N + n];
                    if (g.add2) v += g.add2[(long long)m * g.N + n];
                    if (g.bias) {
                        int nf = g.biasCompact ? (n + (n >= 1024 ? 1024 : 0)) : n;
                        v += g.bias[(long long)z * g.biasz + nf];
                    }
                    if (g.Eg)
                        v += g.Eg[(long long)z * g.Egz +
                                  (long long)(e >= 2 ? tk1 : tk0) * g.N + n];
                    C[(long long)m * g.ldc + n] = v;
                }
            }
        }
    }
}

// ---------------- elementwise stages ----------------
__device__ __forceinline__ void split_bf16(float v, __nv_bfloat16& h, __nv_bfloat16& l)
{
    h = __float2bfloat16(v);
    l = __float2bfloat16(v - __bfloat162float(h));
}

// gate: h = sigmoid(o) * tanh(sigmoid(i) * tanh(gg)); writes bf16 hi/lo state(s)
__device__ void gate_stage(const float* gsrc, long long gz, int zc,
                           __nv_bfloat16* d0h, __nv_bfloat16* d0l, long long d0z,
                           __nv_bfloat16* d1h, __nv_bfloat16* d1l, long long d1z)
{
    int total = zc << 18;
    for (int idx = blockIdx.x * NTHR + threadIdx.x; idx < total; idx += gridDim.x * NTHR) {
        int z   = idx >> 18;
        int rem = idx & ((1 << 18) - 1);
        int m = rem >> 10, j = rem & 1023;
        const float* gp = gsrc + (long long)z * gz + (long long)m * NC;
        float gi = gp[j], gg = gp[1024 + j], go = gp[2048 + j];
        float si = 1.f / (1.f + expf(-gi));
        float so = 1.f / (1.f + expf(-go));
        float v  = so * tanhf(si * tanhf(gg));
        __nv_bfloat16 bh, bl;
        split_bf16(v, bh, bl);
        long long o = (long long)z * d0z + (long long)m * 1024 + j;
        d0h[o] = bh; d0l[o] = bl;
        if (d1h) {
            long long o1 = (long long)z * d1z + (long long)m * 1024 + j;
            d1h[o1] = bh; d1l[o1] = bl;
        }
    }
}

__device__ void reset_stage(const float* hid)
{
    for (int idx = blockIdx.x * NTHR + threadIdx.x; idx < (1 << 18);
         idx += gridDim.x * NTHR) {
        float v = hid[idx];
        __nv_bfloat16 bh, bl;
        split_bf16(v, bh, bl);
#pragma unroll
        for (int z = 0; z < 3; z++) {
            d_h1bh[z * BH + idx] = bh; d_h1bl[z * BH + idx] = bl;
            d_h2bh[z * BH + idx] = bh; d_h2bl[z * BH + idx] = bl;
        }
        d_ctxbh[2 * BH + idx] = bh; d_ctxbl[2 * BH + idx] = bl;
    }
}

__device__ void prep_stage(const float* c)
{
    for (int idx = blockIdx.x * NTHR + threadIdx.x; idx < (16 * 256 * 512);
         idx += gridDim.x * NTHR) {
        int ptr = idx >> 17;
        int rem = idx & 131071;
        int b = rem >> 9, k = rem & 511;
        d_cT[idx] = c[((b << 4) + ptr) * 512 + k];
        int pm = ptr > 0 ? ptr - 1 : 0;
        d_cPrev[idx] = c[((b << 4) + pm) * 512 + k];
    }
}

__device__ void nb1_stage(const float* emb, const float* W1ih, const float* b1)
{
    for (int idx = blockIdx.x * NTHR + threadIdx.x; idx < 3 * 3072;
         idx += gridDim.x * NTHR) {
        int i = idx / 3072, n = idx - (idx / 3072) * 3072;
        int nfull = n + (n >= 1024 ? 1024 : 0);
        const float* e = emb + (long long)i * 130 * 512;            // v = 0 row
        const float* w = W1ih + ((long long)i * 4096 + nfull) * 1024;
        float s = b1[i * 4096 + nfull];
        for (int k = 0; k < 512; k++) s += e[k] * w[k];
        d_nb1[idx] = s;
    }
}

// weight -> compacted bf16 hi/lo
__device__ void convw_stage(const float* src, long long sld, long long sz,
                            int zc, int rows, int K, int compact,
                            __nv_bfloat16* h, __nv_bfloat16* l)
{
    int total = zc * rows * K;
    for (int idx = blockIdx.x * NTHR + threadIdx.x; idx < total;
         idx += gridDim.x * NTHR) {
        int k = idx % K;
        int rz = idx / K;
        int r = rz % rows;
        int z = rz / rows;
        int rf = compact ? (r + (r >= 1024 ? 1024 : 0)) : r;
        float v = src[(long long)z * sz + (long long)rf * sld + k];
        __nv_bfloat16 bh, bl;
        split_bf16(v, bh, bl);
        h[idx] = bh; l[idx] = bl;
    }
}

// ---------------- the single persistent kernel ----------------
__global__ void __launch_bounds__(NTHR, 1)
mega_kernel(const float* c, const float* W1ih, const float* W1hh, const float* b1,
            const float* cWih, const float* cWhh, const float* cb,
            const float* W2ih, const float* W2hh, const float* b2,
            const float* outW, const float* outb,
            const float* hidW, const float* hidb,
            const float* emb, const int* tgt, float* out)
{
    __shared__ __align__(16) char smem_raw[49152];   // 48 KB: 2 x 24576 mma buffers
    float* As = (float*)smem_raw;
    float* Bs = (float*)(smem_raw + 16384 * 2 / 2 + 8192);  // As 8KB @0, Bs 8KB @8192... (see below)
    // preamble uses As @0 (16x128 f32 = 8KB) and Bs @8192 (8KB) — disjoint, within 48KB.
    Bs = (float*)(smem_raw + 8192);
    char* sm = (char*)smem_raw;
    unsigned sb;
    asm("{.reg .u64 t; cvta.to.shared.u64 t, %1; cvt.u32.u64 %0, t;}"
        : "=r"(sb) : "l"(smem_raw));

    // ---- phase 0: transpose + notes0 hoist + weight conversion ----
    prep_stage(c);
    nb1_stage(emb, W1ih, b1);
    convw_stage(W1hh, 1024, 4096LL * 1024, 3, 3072, 1024, 1, d_W1hhbh, d_W1hhbl);
    convw_stage(cWih, 3072, 0,             1, 3072, 3072, 1, d_cWihbh, d_cWihbl);
    convw_stage(cWhh, 1024, 0,             1, 3072, 1024, 1, d_cWhhbh, d_cWhhbl);
    convw_stage(W2ih, 1536, 4096LL * 1536, 3, 3072, 1024, 1, d_W2ihbh, d_W2ihbl);
    convw_stage(W2hh, 1024, 4096LL * 1024, 3, 3072, 1024, 1, d_W2hhbh, d_W2hhbl);
    convw_stage(outW, 1024, 130LL * 1024,  3, 130,  1024, 0, d_outWbh, d_outWbl);
    gsync();

    // ---- phase 1: per-bar hoisted GEMMs (FFMA2 path) ----
    { // hidden[ptr] = tanh(cPrev @ hidW^T + hidb)
        GP g = {};
        g.A = d_cPrev; g.lda = 512; g.B = hidW; g.ldb = 512;
        g.K = 512; g.M = 4096; g.N = 1024; g.zc = 1; g.epi = 1;
        g.C = d_hid; g.ldc = 1024;
        g.bias = hidb;
        gemm_stage(g, As, Bs);
    }
    { // A1[i][ptr] = nb1[i] + cT @ W1ih[i][:,512:]^T
        GP g = {};
        g.A = d_cT; g.lda = 512;
        g.B = W1ih + 512; g.ldb = 1024; g.Bz = 4096LL * 1024;
        g.K = 512; g.M = 4096; g.N = NC; g.zc = 3; g.compact = 1;
        g.C = d_A1; g.ldc = NC; g.Cz = 16LL * GS;
        g.bias = d_nb1; g.biasz = NC;
        gemm_stage(g, As, Bs);
    }
    { // CU[ptr] = cT @ W1ih[1][:,512:]^T + b1[1]
        GP g = {};
        g.A = d_cT; g.lda = 512;
        g.B = W1ih + 4096LL * 1024 + 512; g.ldb = 1024;
        g.K = 512; g.M = 4096; g.N = NC; g.zc = 1; g.compact = 1;
        g.C = d_CU; g.ldc = NC;
        g.bias = b1 + 4096; g.biasCompact = 1;
        gemm_stage(g, As, Bs);
    }
    { // C2[i][ptr] = cT @ W2ih[i][:,1024:]^T + b2[i]
        GP g = {};
        g.A = d_cT; g.lda = 512;
        g.B = W2ih + 1024; g.ldb = 1536; g.Bz = 4096LL * 1536;
        g.K = 512; g.M = 4096; g.N = NC; g.zc = 3; g.compact = 1;
        g.C = d_C2; g.ldc = NC; g.Cz = 16LL * GS;
        g.bias = b2; g.biasz = 4096; g.biasCompact = 1;
        gemm_stage(g, As, Bs);
    }
    { // E = emb @ W1ih[1][:, :512]^T
        GP g = {};
        g.A = emb; g.lda = 512;
        g.B = W1ih + 4096LL * 1024; g.ldb = 1024;
        g.K = 512; g.M = 390; g.N = NC; g.zc = 1; g.compact = 1;
        g.C = d_E; g.ldc = NC;
        gemm_stage(g, As, Bs);
    }
    gsync();

    // ---- time loop (tensor-core path) ----
    for (int t = 0; t < TT; t++) {
        int ptr = t >> 4;
        if ((t & 15) == 0) {
            reset_stage(d_hid + (long long)ptr * BH);
            gsync();
        }

        { // g = A1[.,ptr] + h1 @ W1hh^T
            MGP g = {};
            g.Ah = d_h1bh; g.Al = d_h1bl; g.lda = 1024; g.Az = BH;
            g.Bh = d_W1hhbh; g.Bl = d_W1hhbl; g.ldb = 1024; g.Bz = 3072LL * 1024;
            g.K = 1024; g.M = BB; g.N = NC; g.zc = 3;
            g.C = d_g; g.ldc = NC; g.Cz = GS;
            g.add0 = d_A1 + (long long)ptr * GS; g.add0z = 16LL * GS;
            mma_stage<128>(g, sm, sb);
        }
        gsync();
        gate_stage(d_g, GS, 3, d_h1bh, d_h1bl, BH, d_uobh, d_uobl, BH);
        gsync();

        { // s[i] = uold[i] @ cWih[:, i*1024:]^T
            MGP g = {};
            g.Ah = d_uobh; g.Al = d_uobl; g.lda = 1024; g.Az = BH;
            g.Bh = d_cWihbh; g.Bl = d_cWihbl; g.ldb = 3072; g.Bz = 1024;
            g.K = 1024; g.M = BB; g.N = NC; g.zc = 3;
            g.C = d_s; g.ldc = NC; g.Cz = GS;
            mma_stage<128>(g, sm, sb);
        }
        { // gu[i] = E[i][tok] + CU[ptr] + uold[i] @ W1hh[1]^T   (i = 0,1)
            MGP g = {};
            g.Ah = d_uobh; g.Al = d_uobl; g.lda = 1024; g.Az = BH;
            g.Bh = d_W1hhbh + 3072LL * 1024; g.Bl = d_W1hhbl + 3072LL * 1024;
            g.ldb = 1024; g.Bz = 0;
            g.K = 1024; g.M = BB; g.N = NC; g.zc = 2;
            g.C = d_g; g.ldc = NC; g.Cz = GS;
            g.add0 = d_CU + (long long)ptr * GS; g.add0z = 0;
            g.Eg = d_E; g.Egz = 130LL * NC;
            g.tok = tgt + t; g.tokz = 65536; g.tokstride = 256;
            mma_stage<128>(g, sm, sb);
        }
        gsync();
        gate_stage(d_g, GS, 2, d_unbh, d_unbl, BH, (__nv_bfloat16*)0, (__nv_bfloat16*)0, 0);
        gsync();

        { // sn[i] = unew[i] @ cWih[:, i*1024:]^T  (i = 0,1)
            MGP g = {};
            g.Ah = d_unbh; g.Al = d_unbl; g.lda = 1024; g.Az = BH;
            g.Bh = d_cWihbh; g.Bl = d_cWihbl; g.ldb = 3072; g.Bz = 1024;
            g.K = 1024; g.M = BB; g.N = NC; g.zc = 2;
            g.C = d_sn; g.ldc = NC; g.Cz = GS;
            mma_stage<128>(g, sm, sb);
        }
        { // ctx update 0 (shares phase with sn)
            MGP g = {};
            g.Ah = d_ctxbh + 2LL * BH; g.Al = d_ctxbl + 2LL * BH; g.lda = 1024; g.Az = 0;
            g.Bh = d_cWhhbh; g.Bl = d_cWhhbl; g.ldb = 1024; g.Bz = 0;
            g.K = 1024; g.M = BB; g.N = NC; g.zc = 1;
            g.C = d_g; g.ldc = NC; g.Cz = 0;
            g.add0 = d_s; g.add0z = 0;
            g.add1 = d_s + GS; g.add2 = d_s + 2LL * GS;
            g.bias = cb; g.biasz = 0; g.biasCompact = 1;
            mma_stage<64>(g, sm, sb);
        }
        gsync();
        gate_stage(d_g, 0, 1, d_ctxbh, d_ctxbl, 0, (__nv_bfloat16*)0, (__nv_bfloat16*)0, 0);
        gsync();

        { // ctx update 1
            MGP g = {};
            g.Ah = d_ctxbh; g.Al = d_ctxbl; g.lda = 1024; g.Az = 0;
            g.Bh = d_cWhhbh; g.Bl = d_cWhhbl; g.ldb = 1024; g.Bz = 0;
            g.K = 1024; g.M = BB; g.N = NC; g.zc = 1;
            g.C = d_g; g.ldc = NC; g.Cz = 0;
            g.add0 = d_sn; g.add0z = 0;
            g.add1 = d_s + GS; g.add2 = d_s + 2LL * GS;
            g.bias = cb; g.biasz = 0; g.biasCompact = 1;
            mma_stage<64>(g, sm, sb);
        }
        gsync();
        gate_stage(d_g, 0, 1, d_ctxbh + BH, d_ctxbl + BH, 0,
                   (__nv_bfloat16*)0, (__nv_bfloat16*)0, 0);
        gsync();

        { // ctx update 2
            MGP g = {};
            g.Ah = d_ctxbh + (long long)BH; g.Al = d_ctxbl + (long long)BH;
            g.lda = 1024; g.Az = 0;
            g.Bh = d_cWhhbh; g.Bl = d_cWhhbl; g.ldb = 1024; g.Bz = 0;
            g.K = 1024; g.M = BB; g.N = NC; g.zc = 1;
            g.C = d_g; g.ldc = NC; g.Cz = 0;
            g.add0 = d_sn; g.add0z = 0;
            g.add1 = d_sn + GS; g.add2 = d_s + 2LL * GS;
            g.bias = cb; g.biasz = 0; g.biasCompact = 1;
            mma_stage<64>(g, sm, sb);
        }
        gsync();
        gate_stage(d_g, 0, 1, d_ctxbh + 2LL * BH, d_ctxbl + 2LL * BH, 0,
                   (__nv_bfloat16*)0, (__nv_bfloat16*)0, 0);
        gsync();

        { // g2[i] = ctx[i] @ W2ih[i][:, :1024]^T + h2[i] @ W2hh[i]^T + C2[i][ptr]
            MGP g = {};
            g.Ah = d_ctxbh; g.Al = d_ctxbl; g.lda = 1024; g.Az = BH;
            g.Bh = d_W2ihbh; g.Bl = d_W2ihbl; g.ldb = 1024; g.Bz = 3072LL * 1024;
            g.A2h = d_h2bh; g.A2l = d_h2bl; g.lda2 = 1024; g.A2z = BH;
            g.B2h = d_W2hhbh; g.B2l = d_W2hhbl; g.ldb2 = 1024; g.B2z = 3072LL * 1024;
            g.K = 1024; g.K2 = 1024; g.M = BB; g.N = NC; g.zc = 3;
            g.C = d_g; g.ldc = NC; g.Cz = GS;
            g.add0 = d_C2 + (long long)ptr * GS; g.add0z = 16LL * GS;
            mma_stage<128>(g, sm, sb);
        }
        gsync();
        gate_stage(d_g, GS, 3, d_h2bh, d_h2bl, BH, (__nv_bfloat16*)0, (__nv_bfloat16*)0, 0);
        gsync();

        { // out[i][:,t,:] = (uold[i] + h2[i]) @ outW[i]^T + outb[i]
            MGP g = {};
            g.Ah = d_uobh; g.Al = d_uobl; g.lda = 1024; g.Az = BH;
            g.Bh = d_outWbh; g.Bl = d_outWbl; g.ldb = 1024; g.Bz = 130LL * 1024;
            g.A2h = d_h2bh; g.A2l = d_h2bl; g.lda2 = 1024; g.A2z = BH;
            g.B2h = d_outWbh; g.B2l = d_outWbl; g.ldb2 = 1024; g.B2z = 130LL * 1024;
            g.K = 1024; g.K2 = 1024; g.M = BB; g.N = VV; g.zc = 3;
            g.C = out + (long long)t * VV; g.ldc = (long long)TT * VV;
            g.Cz = (long long)BB * TT * VV;
            g.bias = outb; g.biasz = VV;
            mma_stage<64>(g, sm, sb);
        }
        gsync();   // protects uold/h2 (read by OUT) from next step's writers
    }
}

// ---------------- host ----------------
extern "C" void kernel_launch(void* const* d_in, const int* in_sizes, int n_in,
                              void* d_out, int out_size)
{
    (void)in_sizes; (void)n_in; (void)out_size;
    mega_kernel<<<NBLK, NTHR>>>(
        (const float*)d_in[0],  (const float*)d_in[1],  (const float*)d_in[2],
        (const float*)d_in[3],  (const float*)d_in[4],  (const float*)d_in[5],
        (const float*)d_in[6],  (const float*)d_in[7],  (const float*)d_in[8],
        (const float*)d_in[9],  (const float*)d_in[10], (const float*)d_in[11],
        (const float*)d_in[12], (const float*)d_in[13], (const float*)d_in[14],
        (const int*)d_in[15],   (float*)d_out);
}

// round 11
// speedup vs baseline: 3.5211x; 1.0326x over previous
#include <cuda_runtime.h>
#include <cuda_bf16.h>
#include <cstdint>

// ---------------- problem constants ----------------
#define NBLK 148
#define NTHR 512
#define BB   256
#define NC   3072            // compact gate width (i, gg, o) -- f gate is dead
#define TT   256
#define VV   130
#define BH   (256*1024)
#define GS   (256*3072)
#define ASLAB 131072         // uints per activation fragment slab (256x1024/2)
#define WNF  384             // n-frags per z for 3072-row weight matrices
#define WZS  (WNF*4096)      // uints per z for 3072-row weights (NF*64ks*64)

// ---------------- persistent device scratch (fp32) ----------------
__device__ float d_cT   [16*256*512];
__device__ float d_cPrev[16*256*512];
__device__ float d_hid  [16*256*1024];
__device__ float d_A1   [3*16*256*3072];
__device__ float d_CU   [16*256*3072];
__device__ float d_C2   [3*16*256*3072];
__device__ float d_E    [3*130*3072];
__device__ float d_nb1  [3*3072];
__device__ float d_s    [3*256*3072];
__device__ float d_sn   [2*256*3072];
__device__ float d_g    [3*256*3072];

// ---------------- fragment-layout weights (hi/lo split bf16, packed uints) --
__device__ unsigned d_W1hhf_h[3*WZS], d_W1hhf_l[3*WZS];
__device__ unsigned d_cWihf_h[3*WZS], d_cWihf_l[3*WZS];
__device__ unsigned d_cWhhf_h[1*WZS], d_cWhhf_l[1*WZS];
__device__ unsigned d_W2ihf_h[3*WZS], d_W2ihf_l[3*WZS];
__device__ unsigned d_W2hhf_h[3*WZS], d_W2hhf_l[3*WZS];
__device__ unsigned d_outWf_h[3*32*4096], d_outWf_l[3*32*4096];  // padded 32 frags

// ---------------- fragment-layout activations ----------------
__device__ unsigned d_h1f_h [3*ASLAB], d_h1f_l [3*ASLAB];
__device__ unsigned d_h2f_h [3*ASLAB], d_h2f_l [3*ASLAB];
__device__ unsigned d_ctxf_h[3*ASLAB], d_ctxf_l[3*ASLAB];
__device__ unsigned d_uof_h [3*ASLAB], d_uof_l [3*ASLAB];
__device__ unsigned d_unf_h [2*ASLAB], d_unf_l [2*ASLAB];

// ---------------- grid barrier (replay-safe, sense via generation) ----------
__device__ unsigned int g_arrive;
__device__ unsigned int g_gen;

__device__ __forceinline__ void gsync()
{
    __threadfence();
    __syncthreads();
    if (threadIdx.x == 0) {
        volatile unsigned int* vg = &g_gen;
        unsigned int g = *vg;
        if (atomicAdd(&g_arrive, 1u) == (unsigned)(gridDim.x - 1)) {
            g_arrive = 0;
            __threadfence();
            *vg = g + 1u;
        } else {
            while (*vg == g) __nanosleep(32);
        }
        __threadfence();
    }
    __syncthreads();
}

// ---------------- f32x2 helpers (preamble FFMA2 path) ----------------
__device__ __forceinline__ void fma2(unsigned long long &c, unsigned long long a,
                                     unsigned long long b) {
    asm("fma.rn.f32x2 %0, %1, %2, %0;" : "+l"(c) : "l"(a), "l"(b));
}
__device__ __forceinline__ void unpack2(unsigned long long v, float &lo, float &hi) {
    asm("mov.b64 {%0, %1}, %2;" : "=f"(lo), "=f"(hi) : "l"(v));
}
__device__ __forceinline__ unsigned long long dup2(float a) {
    unsigned long long r;
    asm("mov.b64 %0, {%1, %1};" : "=l"(r) : "f"(a));
    return r;
}

// ---------------- mma helper ----------------
__device__ __forceinline__ void mma16816(float* d, const unsigned* a, const unsigned* b) {
    asm volatile("mma.sync.aligned.m16n8k16.row.col.f32.bf16.bf16.f32 "
                 "{%0,%1,%2,%3},{%4,%5,%6,%7},{%8,%9},{%0,%1,%2,%3};"
                 : "+f"(d[0]), "+f"(d[1]), "+f"(d[2]), "+f"(d[3])
                 : "r"(a[0]), "r"(a[1]), "r"(a[2]), "r"(a[3]), "r"(b[0]), "r"(b[1]));
}

// ---------------- split/pack helpers ----------------
__device__ __forceinline__ void pack_split(float v0, float v1, unsigned& hi, unsigned& lo)
{
    __nv_bfloat16 h0 = __float2bfloat16(v0);
    __nv_bfloat16 h1 = __float2bfloat16(v1);
    __nv_bfloat16 l0 = __float2bfloat16(v0 - __bfloat162float(h0));
    __nv_bfloat16 l1 = __float2bfloat16(v1 - __bfloat162float(h1));
    hi = (unsigned)__bfloat16_as_ushort(h0) | ((unsigned)__bfloat16_as_ushort(h1) << 16);
    lo = (unsigned)__bfloat16_as_ushort(l0) | ((unsigned)__bfloat16_as_ushort(l1) << 16);
}

__device__ __forceinline__ float gatef(float gi, float gg, float go)
{
    float si = 1.f / (1.f + expf(-gi));
    float so = 1.f / (1.f + expf(-go));
    return so * tanhf(si * tanhf(gg));
}

// ================= preamble FFMA2 GEMM (512-thread) =================
struct GP {
    const float* A;  long long lda,  Az;
    const float* B;  long long ldb,  Bz;
    int K, M, N, zc, compact, epi;
    float* C; long long ldc, Cz;
    const float* bias; long long biasz; int biasCompact;
};

__device__ __forceinline__ void run_mm(const float* A, long long lda, int M, int m0,
                                       const float* Bb, long long ldb, int N, int n0, int K,
                                       float* As, float* Bs,
                                       unsigned long long (*acc)[4],
                                       int tid, int tx, int ty)
{
    int nIter = K >> 4;
    int row = tid >> 2, kq = (tid & 3) << 2;
    for (int it = 0; it < nIter; it++) {
        int k0 = it << 4;
        float4 ra = (m0 + row < M)
            ? *(const float4*)(A + (long long)(m0 + row) * lda + k0 + kq)
            : make_float4(0.f, 0.f, 0.f, 0.f);
        float4 rb = (n0 + row < N)
            ? *(const float4*)(Bb + (long long)row * ldb + k0 + kq)
            : make_float4(0.f, 0.f, 0.f, 0.f);
        __syncthreads();
        As[(kq + 0) * 128 + row] = ra.x;
        As[(kq + 1) * 128 + row] = ra.y;
        As[(kq + 2) * 128 + row] = ra.z;
        As[(kq + 3) * 128 + row] = ra.w;
        Bs[(kq + 0) * 128 + row] = rb.x;
        Bs[(kq + 1) * 128 + row] = rb.y;
        Bs[(kq + 2) * 128 + row] = rb.z;
        Bs[(kq + 3) * 128 + row] = rb.w;
        __syncthreads();
#pragma unroll
        for (int kk = 0; kk < 16; kk++) {
            ulonglong2 b01 = *(const ulonglong2*)&Bs[kk * 128 + tx * 8];
            ulonglong2 b23 = *(const ulonglong2*)&Bs[kk * 128 + tx * 8 + 4];
            ulonglong2 ap  = *(const ulonglong2*)&As[kk * 128 + ty * 4];
            float av[4];
            unpack2(ap.x, av[0], av[1]);
            unpack2(ap.y, av[2], av[3]);
#pragma unroll
            for (int mi = 0; mi < 4; mi++) {
                unsigned long long a2 = dup2(av[mi]);
                fma2(acc[mi][0], b01.x, a2);
                fma2(acc[mi][1], b01.y, a2);
                fma2(acc[mi][2], b23.x, a2);
                fma2(acc[mi][3], b23.y, a2);
            }
        }
    }
    __syncthreads();
}

__device__ void gemm_stage(const GP& g, float* As, float* Bs)
{
    int mT = (g.M + 127) >> 7;
    int nT = (g.N + 127) >> 7;
    int total = g.zc * mT * nT;
    int tid = threadIdx.x;
    int tx = tid & 15, ty = tid >> 4;

    for (int tile = blockIdx.x; tile < total; tile += gridDim.x) {
        int z  = tile / (mT * nT);
        int r  = tile - z * (mT * nT);
        int m0 = (r / nT) << 7;
        int n0 = (r % nT) << 7;
        int noff = (g.compact && n0 >= 1024) ? 1024 : 0;

        unsigned long long acc[4][4];
#pragma unroll
        for (int i = 0; i < 4; i++)
#pragma unroll
            for (int j = 0; j < 4; j++) acc[i][j] = 0ull;

        const float* A  = g.A + (long long)z * g.Az;
        const float* Bb = g.B + (long long)z * g.Bz + (long long)(n0 + noff) * g.ldb;
        run_mm(A, g.lda, g.M, m0, Bb, g.ldb, g.N, n0, g.K, As, Bs, acc, tid, tx, ty);

        float* C = g.C + (long long)z * g.Cz;
#pragma unroll
        for (int mi = 0; mi < 4; mi++) {
            int m = m0 + ty * 4 + mi;
            if (m >= g.M) continue;
            float cv[8];
#pragma unroll
            for (int jj = 0; jj < 4; jj++)
                unpack2(acc[mi][jj], cv[2 * jj], cv[2 * jj + 1]);
#pragma unroll
            for (int nj = 0; nj < 8; nj++) {
                int n = n0 + tx * 8 + nj;
                if (n >= g.N) continue;
                float v = cv[nj];
                if (g.bias) v += g.bias[(long long)z * g.biasz + (g.biasCompact ? (n + noff) : n)];
                if (g.epi == 1) v = tanhf(v);
                C[(long long)m * g.ldc + n] = v;
            }
        }
    }
}

// ================= fragment-direct tensor-core GEMM (time loop) ============
// A frag slab layout: uint index = ((mf*64 + ks)*32 + lane)*4 + reg,  mf=m>>4
//   reg r: row = mf*16 + (lane>>2) + (r&1)*8 ; k = ks*16 + (r>>1)*8 + (lane&3)*2 (+pair)
// B frag layout:      uint index = ((nf*64 + ks)*64 + lane*2 + reg), nf=n>>3
//   reg r: n = nf*8 + (lane>>2) ; k = ks*16 + r*8 + (lane&3)*2 (+pair)
struct MGP {
    const unsigned *Ah, *Al;   long long Az;   // slab stride (uints)
    const unsigned *Bh, *Bl;   long long Bz;   // per-z frag stride (uints)
    const unsigned *A2h, *A2l; long long A2z;
    const unsigned *B2h, *B2l; long long B2z;
    int M, N, zc;                               // K fixed = 1024 (64 k-slices)
    float* C; long long ldc, Cz;
    const float* add0; long long add0z;
    const float *add1, *add2;
    const float* bias; long long biasz; int biasCompact;
    const float* Eg;  long long Egz;
    const int*  tok;  long long tokz;  int tokstride;
};

template<int TM>
__device__ __forceinline__ void mma_runf(
    const unsigned* Ah, const unsigned* Al,
    const unsigned* Bh, const unsigned* Bl,
    int m0, int n0, float* d, int wm, int wn, int L)
{
    constexpr int NT = (TM == 128) ? 4 : 2;
    int mf0 = (m0 >> 4) + wm * 2;
    int nf0 = (n0 >> 3) + wn * NT;
    const unsigned* paH0 = Ah + ((long long)(mf0 + 0) * 64) * 128 + L * 4;
    const unsigned* paH1 = Ah + ((long long)(mf0 + 1) * 64) * 128 + L * 4;
    const unsigned* paL0 = Al + ((long long)(mf0 + 0) * 64) * 128 + L * 4;
    const unsigned* paL1 = Al + ((long long)(mf0 + 1) * 64) * 128 + L * 4;
    const unsigned* pbH[NT];
    const unsigned* pbL[NT];
#pragma unroll
    for (int nt = 0; nt < NT; nt++) {
        pbH[nt] = Bh + ((long long)(nf0 + nt) * 64) * 64 + L * 2;
        pbL[nt] = Bl + ((long long)(nf0 + nt) * 64) * 64 + L * 2;
    }

    uint2 bhC[NT], blC[NT];
#pragma unroll
    for (int nt = 0; nt < NT; nt++) {
        bhC[nt] = *(const uint2*)(pbH[nt]);
        blC[nt] = *(const uint2*)(pbL[nt]);
    }

#pragma unroll 2
    for (int ks = 0; ks < 64; ks++) {
        uint2 bhN[NT], blN[NT];
        if (ks < 63) {
#pragma unroll
            for (int nt = 0; nt < NT; nt++) {
                bhN[nt] = *(const uint2*)(pbH[nt] + (ks + 1) * 64);
                blN[nt] = *(const uint2*)(pbL[nt] + (ks + 1) * 64);
            }
        }
        uint4 ah0 = *(const uint4*)(paH0 + ks * 128);
        uint4 ah1 = *(const uint4*)(paH1 + ks * 128);
        uint4 al0 = *(const uint4*)(paL0 + ks * 128);
        uint4 al1 = *(const uint4*)(paL1 + ks * 128);
#pragma unroll
        for (int nt = 0; nt < NT; nt++) {
            float* d0 = d + nt * 4;
            float* d1 = d + (NT + nt) * 4;
            mma16816(d0, (const unsigned*)&ah0, (const unsigned*)&bhC[nt]);
            mma16816(d0, (const unsigned*)&ah0, (const unsigned*)&blC[nt]);
            mma16816(d0, (const unsigned*)&al0, (const unsigned*)&bhC[nt]);
            mma16816(d1, (const unsigned*)&ah1, (const unsigned*)&bhC[nt]);
            mma16816(d1, (const unsigned*)&ah1, (const unsigned*)&blC[nt]);
            mma16816(d1, (const unsigned*)&al1, (const unsigned*)&bhC[nt]);
        }
#pragma unroll
        for (int nt = 0; nt < NT; nt++) { bhC[nt] = bhN[nt]; blC[nt] = blN[nt]; }
    }
}

template<int TM>
__device__ void mma_stage(const MGP& g)
{
    constexpr int NT = (TM == 128) ? 4 : 2;
    constexpr int NW = NT * 8;
    int mT = (g.M + TM - 1) / TM;
    int nT = (g.N + 127) >> 7;
    int total = g.zc * mT * nT;
    int tid = threadIdx.x, w = tid >> 5, L = tid & 31;
    int wm = (TM == 128) ? (w >> 2) : (w >> 3);
    int wn = (TM == 128) ? (w & 3) : (w & 7);

    for (int tile = blockIdx.x; tile < total; tile += gridDim.x) {
        int z  = tile / (mT * nT);
        int r  = tile - z * (mT * nT);
        int m0 = (r / nT) * TM;
        int n0 = (r % nT) << 7;

        float d[2 * NT * 4];
#pragma unroll
        for (int i = 0; i < 2 * NT * 4; i++) d[i] = 0.f;

        mma_runf<TM>(g.Ah + (long long)z * g.Az, g.Al + (long long)z * g.Az,
                     g.Bh + (long long)z * g.Bz, g.Bl + (long long)z * g.Bz,
                     m0, n0, d, wm, wn, L);
        if (g.A2h)
            mma_runf<TM>(g.A2h + (long long)z * g.A2z, g.A2l + (long long)z * g.A2z,
                         g.B2h + (long long)z * g.B2z, g.B2l + (long long)z * g.B2z,
                         m0, n0, d, wm, wn, L);

        float* C = g.C + (long long)z * g.Cz;
#pragma unroll
        for (int mt = 0; mt < 2; mt++) {
            int rbase = m0 + wm * 32 + mt * 16 + (L >> 2);
            int tk0 = 0, tk1 = 0;
            if (g.Eg) {
                tk0 = g.tok[(long long)z * g.tokz + (long long)rbase * g.tokstride];
                tk1 = g.tok[(long long)z * g.tokz + (long long)(rbase + 8) * g.tokstride];
            }
#pragma unroll
            for (int nt = 0; nt < NT; nt++) {
                const float* dd = d + (mt * NT + nt) * 4;
                int cbase = n0 + wn * NW + nt * 8 + (L & 3) * 2;
#pragma unroll
                for (int e = 0; e < 4; e++) {
                    int m = rbase + (e >= 2 ? 8 : 0);
                    int n = cbase + (e & 1);
                    if (n >= g.N || m >= g.M) continue;
                    float v = dd[e];
                    if (g.add0) v += g.add0[(long long)z * g.add0z + (long long)m * g.N + n];
                    if (g.add1) v += g.add1[(long long)m * g.N + n];
                    if (g.add2) v += g.add2[(long long)m * g.N + n];
                    if (g.bias) {
                        int nf = g.biasCompact ? (n + (n >= 1024 ? 1024 : 0)) : n;
                        v += g.bias[(long long)z * g.biasz + nf];
                    }
                    if (g.Eg)
                        v += g.Eg[(long long)z * g.Egz +
                                  (long long)(e >= 2 ? tk1 : tk0) * g.N + n];
                    C[(long long)m * g.ldc + n] = v;
                }
            }
        }
    }
}

// ---------------- elementwise stages (fragment writers) ----------------
// gate: reads fp32 g (compact [i|gg|o]), writes activation frag slab(s)
__device__ void gate_stagef(const float* gsrc, long long gz, int zc,
                            unsigned* d0h, unsigned* d0l,
                            unsigned* d1h, unsigned* d1l)
{
    int total = zc * ASLAB;
    for (int idx = blockIdx.x * NTHR + threadIdx.x; idx < total; idx += gridDim.x * NTHR) {
        int u = idx & (ASLAB - 1);
        int z = idx >> 17;
        int r = u & 3, l = (u >> 2) & 31, ks = (u >> 7) & 63, mf = u >> 13;
        int m  = mf * 16 + (l >> 2) + (r & 1) * 8;
        int k0 = ks * 16 + ((r >> 1) & 1) * 8 + (l & 3) * 2;
        const float* gp = gsrc + (long long)z * gz + (long long)m * NC;
        float v0 = gatef(gp[k0],     gp[1024 + k0],     gp[2048 + k0]);
        float v1 = gatef(gp[k0 + 1], gp[1024 + k0 + 1], gp[2048 + k0 + 1]);
        unsigned hi, lo;
        pack_split(v0, v1, hi, lo);
        d0h[(long long)z * ASLAB + u] = hi;
        d0l[(long long)z * ASLAB + u] = lo;
        if (d1h) {
            d1h[(long long)z * ASLAB + u] = hi;
            d1l[(long long)z * ASLAB + u] = lo;
        }
    }
}

__device__ void reset_stagef(const float* hid)
{
    for (int u = blockIdx.x * NTHR + threadIdx.x; u < ASLAB; u += gridDim.x * NTHR) {
        int r = u & 3, l = (u >> 2) & 31, ks = (u >> 7) & 63, mf = u >> 13;
        int m  = mf * 16 + (l >> 2) + (r & 1) * 8;
        int k0 = ks * 16 + ((r >> 1) & 1) * 8 + (l & 3) * 2;
        const float* hp = hid + (long long)m * 1024 + k0;
        unsigned hi, lo;
        pack_split(hp[0], hp[1], hi, lo);
#pragma unroll
        for (int z = 0; z < 3; z++) {
            d_h1f_h[z * ASLAB + u] = hi; d_h1f_l[z * ASLAB + u] = lo;
            d_h2f_h[z * ASLAB + u] = hi; d_h2f_l[z * ASLAB + u] = lo;
        }
        d_ctxf_h[2 * ASLAB + u] = hi; d_ctxf_l[2 * ASLAB + u] = lo;
    }
}

__device__ void prep_stage(const float* c)
{
    for (int idx = blockIdx.x * NTHR + threadIdx.x; idx < (16 * 256 * 512);
         idx += gridDim.x * NTHR) {
        int ptr = idx >> 17;
        int rem = idx & 131071;
        int b = rem >> 9, k = rem & 511;
        d_cT[idx] = c[((b << 4) + ptr) * 512 + k];
        int pm = ptr > 0 ? ptr - 1 : 0;
        d_cPrev[idx] = c[((b << 4) + pm) * 512 + k];
    }
}

__device__ void nb1_stage(const float* emb, const float* W1ih, const float* b1)
{
    for (int idx = blockIdx.x * NTHR + threadIdx.x; idx < 3 * 3072;
         idx += gridDim.x * NTHR) {
        int i = idx / 3072, n = idx - (idx / 3072) * 3072;
        int nfull = n + (n >= 1024 ? 1024 : 0);
        const float* e = emb + (long long)i * 130 * 512;            // v = 0 row
        const float* w = W1ih + ((long long)i * 4096 + nfull) * 1024;
        float s = b1[i * 4096 + nfull];
        for (int k = 0; k < 512; k++) s += e[k] * w[k];
        d_nb1[idx] = s;
    }
}

// weight -> fragment-layout bf16 hi/lo
__device__ void convw_frag(const float* src, long long sld, long long sz, int kstep,
                           int zc, int Nvalid, int NF, int compact,
                           unsigned* H, unsigned* Lo)
{
    int total = zc * NF * 4096;
    for (int idx = blockIdx.x * NTHR + threadIdx.x; idx < total;
         idx += gridDim.x * NTHR) {
        int r  = idx & 1;
        int l  = (idx >> 1) & 31;
        int ks = (idx >> 6) & 63;
        int rest = idx >> 12;                   // z*NF + nf
        int nf = rest % NF, z = rest / NF;
        int n = nf * 8 + (l >> 2);
        int k = ks * 16 + r * 8 + (l & 3) * 2;
        float v0 = 0.f, v1 = 0.f;
        if (n < Nvalid) {
            int nfull = compact ? (n + (n >= 1024 ? 1024 : 0)) : n;
            const float* p = src + (long long)z * sz + (long long)nfull * sld
                           + k + (long long)z * kstep;
            v0 = p[0]; v1 = p[1];
        }
        unsigned hi, lo;
        pack_split(v0, v1, hi, lo);
        H[idx] = hi; Lo[idx] = lo;
    }
}

// ---------------- the single persistent kernel ----------------
__global__ void __launch_bounds__(NTHR, 1)
mega_kernel(const float* c, const float* W1ih, const float* W1hh, const float* b1,
            const float* cWih, const float* cWhh, const float* cb,
            const float* W2ih, const float* W2hh, const float* b2,
            const float* outW, const float* outb,
            const float* hidW, const float* hidb,
            const float* emb, const int* tgt, float* out)
{
    __shared__ __align__(16) float As[2048];   // preamble FFMA2 staging only
    __shared__ __align__(16) float Bs[2048];

    // ---- phase 0: transpose + notes0 hoist + weight fragment conversion ----
    prep_stage(c);
    nb1_stage(emb, W1ih, b1);
    convw_frag(W1hh, 1024, 4096LL * 1024, 0,    3, 3072, WNF, 1, d_W1hhf_h, d_W1hhf_l);
    convw_frag(cWih, 3072, 0,             1024, 3, 3072, WNF, 1, d_cWihf_h, d_cWihf_l);
    convw_frag(cWhh, 1024, 0,             0,    1, 3072, WNF, 1, d_cWhhf_h, d_cWhhf_l);
    convw_frag(W2ih, 1536, 4096LL * 1536, 0,    3, 3072, WNF, 1, d_W2ihf_h, d_W2ihf_l);
    convw_frag(W2hh, 1024, 4096LL * 1024, 0,    3, 3072, WNF, 1, d_W2hhf_h, d_W2hhf_l);
    convw_frag(outW, 1024, 130LL * 1024,  0,    3, 130,  32,  0, d_outWf_h, d_outWf_l);
    gsync();

    // ---- phase 1: per-bar hoisted GEMMs (FFMA2 path) ----
    { // hidden[ptr] = tanh(cPrev @ hidW^T + hidb)
        GP g = {};
        g.A = d_cPrev; g.lda = 512; g.B = hidW; g.ldb = 512;
        g.K = 512; g.M = 4096; g.N = 1024; g.zc = 1; g.epi = 1;
        g.C = d_hid; g.ldc = 1024;
        g.bias = hidb;
        gemm_stage(g, As, Bs);
    }
    { // A1[i][ptr] = nb1[i] + cT @ W1ih[i][:,512:]^T
        GP g = {};
        g.A = d_cT; g.lda = 512;
        g.B = W1ih + 512; g.ldb = 1024; g.Bz = 4096LL * 1024;
        g.K = 512; g.M = 4096; g.N = NC; g.zc = 3; g.compact = 1;
        g.C = d_A1; g.ldc = NC; g.Cz = 16LL * GS;
        g.bias = d_nb1; g.biasz = NC;
        gemm_stage(g, As, Bs);
    }
    { // CU[ptr] = cT @ W1ih[1][:,512:]^T + b1[1]
        GP g = {};
        g.A = d_cT; g.lda = 512;
        g.B = W1ih + 4096LL * 1024 + 512; g.ldb = 1024;
        g.K = 512; g.M = 4096; g.N = NC; g.zc = 1; g.compact = 1;
        g.C = d_CU; g.ldc = NC;
        g.bias = b1 + 4096; g.biasCompact = 1;
        gemm_stage(g, As, Bs);
    }
    { // C2[i][ptr] = cT @ W2ih[i][:,1024:]^T + b2[i]
        GP g = {};
        g.A = d_cT; g.lda = 512;
        g.B = W2ih + 1024; g.ldb = 1536; g.Bz = 4096LL * 1536;
        g.K = 512; g.M = 4096; g.N = NC; g.zc = 3; g.compact = 1;
        g.C = d_C2; g.ldc = NC; g.Cz = 16LL * GS;
        g.bias = b2; g.biasz = 4096; g.biasCompact = 1;
        gemm_stage(g, As, Bs);
    }
    { // E = emb @ W1ih[1][:, :512]^T
        GP g = {};
        g.A = emb; g.lda = 512;
        g.B = W1ih + 4096LL * 1024; g.ldb = 1024;
        g.K = 512; g.M = 390; g.N = NC; g.zc = 1; g.compact = 1;
        g.C = d_E; g.ldc = NC;
        gemm_stage(g, As, Bs);
    }
    gsync();

    // ---- time loop (fragment-direct tensor-core path) ----
    for (int t = 0; t < TT; t++) {
        int ptr = t >> 4;
        if ((t & 15) == 0) {
            reset_stagef(d_hid + (long long)ptr * BH);
            gsync();
        }

        { // g = A1[.,ptr] + h1 @ W1hh^T
            MGP g = {};
            g.Ah = d_h1f_h; g.Al = d_h1f_l; g.Az = ASLAB;
            g.Bh = d_W1hhf_h; g.Bl = d_W1hhf_l; g.Bz = WZS;
            g.M = BB; g.N = NC; g.zc = 3;
            g.C = d_g; g.ldc = NC; g.Cz = GS;
            g.add0 = d_A1 + (long long)ptr * GS; g.add0z = 16LL * GS;
            mma_stage<128>(g);
        }
        gsync();
        gate_stagef(d_g, GS, 3, d_h1f_h, d_h1f_l, d_uof_h, d_uof_l);
        gsync();

        { // s[i] = uold[i] @ cWih[:, i*1024:]^T
            MGP g = {};
            g.Ah = d_uof_h; g.Al = d_uof_l; g.Az = ASLAB;
            g.Bh = d_cWihf_h; g.Bl = d_cWihf_l; g.Bz = WZS;
            g.M = BB; g.N = NC; g.zc = 3;
            g.C = d_s; g.ldc = NC; g.Cz = GS;
            mma_stage<128>(g);
        }
        { // gu[i] = E[i][tok] + CU[ptr] + uold[i] @ W1hh[1]^T   (i = 0,1)
            MGP g = {};
            g.Ah = d_uof_h; g.Al = d_uof_l; g.Az = ASLAB;
            g.Bh = d_W1hhf_h + 1LL * WZS; g.Bl = d_W1hhf_l + 1LL * WZS; g.Bz = 0;
            g.M = BB; g.N = NC; g.zc = 2;
            g.C = d_g; g.ldc = NC; g.Cz = GS;
            g.add0 = d_CU + (long long)ptr * GS; g.add0z = 0;
            g.Eg = d_E; g.Egz = 130LL * NC;
            g.tok = tgt + t; g.tokz = 65536; g.tokstride = 256;
            mma_stage<128>(g);
        }
        gsync();
        gate_stagef(d_g, GS, 2, d_unf_h, d_unf_l, (unsigned*)0, (unsigned*)0);
        gsync();

        { // sn[i] = unew[i] @ cWih[:, i*1024:]^T  (i = 0,1)
            MGP g = {};
            g.Ah = d_unf_h; g.Al = d_unf_l; g.Az = ASLAB;
            g.Bh = d_cWihf_h; g.Bl = d_cWihf_l; g.Bz = WZS;
            g.M = BB; g.N = NC; g.zc = 2;
            g.C = d_sn; g.ldc = NC; g.Cz = GS;
            mma_stage<128>(g);
        }
        { // ctx update 0 (shares phase with sn)
            MGP g = {};
            g.Ah = d_ctxf_h + 2LL * ASLAB; g.Al = d_ctxf_l + 2LL * ASLAB; g.Az = 0;
            g.Bh = d_cWhhf_h; g.Bl = d_cWhhf_l; g.Bz = 0;
            g.M = BB; g.N = NC; g.zc = 1;
            g.C = d_g; g.ldc = NC; g.Cz = 0;
            g.add0 = d_s; g.add0z = 0;
            g.add1 = d_s + GS; g.add2 = d_s + 2LL * GS;
            g.bias = cb; g.biasz = 0; g.biasCompact = 1;
            mma_stage<64>(g);
        }
        gsync();
        gate_stagef(d_g, 0, 1, d_ctxf_h, d_ctxf_l, (unsigned*)0, (unsigned*)0);
        gsync();

        { // ctx update 1
            MGP g = {};
            g.Ah = d_ctxf_h; g.Al = d_ctxf_l; g.Az = 0;
            g.Bh = d_cWhhf_h; g.Bl = d_cWhhf_l; g.Bz = 0;
            g.M = BB; g.N = NC; g.zc = 1;
            g.C = d_g; g.ldc = NC; g.Cz = 0;
            g.add0 = d_sn; g.add0z = 0;
            g.add1 = d_s + GS; g.add2 = d_s + 2LL * GS;
            g.bias = cb; g.biasz = 0; g.biasCompact = 1;
            mma_stage<64>(g);
        }
        gsync();
        gate_stagef(d_g, 0, 1, d_ctxf_h + ASLAB, d_ctxf_l + ASLAB,
                    (unsigned*)0, (unsigned*)0);
        gsync();

        { // ctx update 2
            MGP g = {};
            g.Ah = d_ctxf_h + 1LL * ASLAB; g.Al = d_ctxf_l + 1LL * ASLAB; g.Az = 0;
            g.Bh = d_cWhhf_h; g.Bl = d_cWhhf_l; g.Bz = 0;
            g.M = BB; g.N = NC; g.zc = 1;
            g.C = d_g; g.ldc = NC; g.Cz = 0;
            g.add0 = d_sn; g.add0z = 0;
            g.add1 = d_sn + GS; g.add2 = d_s + 2LL * GS;
            g.bias = cb; g.biasz = 0; g.biasCompact = 1;
            mma_stage<64>(g);
        }
        gsync();
        gate_stagef(d_g, 0, 1, d_ctxf_h + 2LL * ASLAB, d_ctxf_l + 2LL * ASLAB,
                    (unsigned*)0, (unsigned*)0);
        gsync();

        { // g2[i] = ctx[i] @ W2ih[i][:, :1024]^T + h2[i] @ W2hh[i]^T + C2[i][ptr]
            MGP g = {};
            g.Ah = d_ctxf_h; g.Al = d_ctxf_l; g.Az = ASLAB;
            g.Bh = d_W2ihf_h; g.Bl = d_W2ihf_l; g.Bz = WZS;
            g.A2h = d_h2f_h; g.A2l = d_h2f_l; g.A2z = ASLAB;
            g.B2h = d_W2hhf_h; g.B2l = d_W2hhf_l; g.B2z = WZS;
            g.M = BB; g.N = NC; g.zc = 3;
            g.C = d_g; g.ldc = NC; g.Cz = GS;
            g.add0 = d_C2 + (long long)ptr * GS; g.add0z = 16LL * GS;
            mma_stage<128>(g);
        }
        gsync();
        gate_stagef(d_g, GS, 3, d_h2f_h, d_h2f_l, (unsigned*)0, (unsigned*)0);
        gsync();

        { // out[i][:,t,:] = (uold[i] + h2[i]) @ outW[i]^T + outb[i]
            MGP g = {};
            g.Ah = d_uof_h; g.Al = d_uof_l; g.Az = ASLAB;
            g.Bh = d_outWf_h; g.Bl = d_outWf_l; g.Bz = 32LL * 4096;
            g.A2h = d_h2f_h; g.A2l = d_h2f_l; g.A2z = ASLAB;
            g.B2h = d_outWf_h; g.B2l = d_outWf_l; g.B2z = 32LL * 4096;
            g.M = BB; g.N = VV; g.zc = 3;
            g.C = out + (long long)t * VV; g.ldc = (long long)TT * VV;
            g.Cz = (long long)BB * TT * VV;
            g.bias = outb; g.biasz = VV;
            mma_stage<64>(g);
        }
        gsync();   // protects uold/h2 (read by OUT) from next step's writers
    }
}

// ---------------- host ----------------
extern "C" void kernel_launch(void* const* d_in, const int* in_sizes, int n_in,
                              void* d_out, int out_size)
{
    (void)in_sizes; (void)n_in; (void)out_size;
    mega_kernel<<<NBLK, NTHR>>>(
        (const float*)d_in[0],  (const float*)d_in[1],  (const float*)d_in[2],
        (const float*)d_in[3],  (const float*)d_in[4],  (const float*)d_in[5],
        (const float*)d_in[6],  (const float*)d_in[7],  (const float*)d_in[8],
        (const float*)d_in[9],  (const float*)d_in[10], (const float*)d_in[11],
        (const float*)d_in[12], (const float*)d_in[13], (const float*)d_in[14],
        (const int*)d_in[15],   (float*)d_out);
}

// round 12
// speedup vs baseline: 3.9365x; 1.1180x over previous
#include <cuda_runtime.h>
#include <cuda_bf16.h>
#include <cstdint>

// ---------------- problem constants ----------------
#define NBLK 148
#define NTHR 512
#define BB   256
#define NC   3072            // compact gate width (i, gg, o) -- f gate is dead
#define TT   256
#define VV   130
#define BH   (256*1024)
#define GS   (256*3072)
#define ASLAB 131072         // uints per activation fragment slab (256x1024/2)
#define WNF  384             // n-frags per z for 3072-row weight matrices
#define WZS  (WNF*4096)      // uints per z for 3072-row weights

// ---------------- persistent device scratch (fp32) ----------------
__device__ float d_cT   [16*256*512];
__device__ float d_cPrev[16*256*512];
__device__ float d_hid  [16*256*1024];
__device__ float d_A1   [3*16*256*3072];
__device__ float d_CU   [16*256*3072];
__device__ float d_C2   [3*16*256*3072];
__device__ float d_E    [3*130*3072];
__device__ float d_nb1  [3*3072];
__device__ float d_s    [3*256*3072];
__device__ float d_sn   [2*256*3072];
__device__ float d_g    [3*256*3072];

// ---------------- fragment-layout weights (hi/lo split bf16, packed uints) --
__device__ unsigned d_W1hhf_h[3*WZS], d_W1hhf_l[3*WZS];
__device__ unsigned d_cWihf_h[3*WZS], d_cWihf_l[3*WZS];
__device__ unsigned d_cWhhf_h[1*WZS], d_cWhhf_l[1*WZS];
__device__ unsigned d_W2ihf_h[3*WZS], d_W2ihf_l[3*WZS];
__device__ unsigned d_W2hhf_h[3*WZS], d_W2hhf_l[3*WZS];
__device__ unsigned d_outWf_h[3*32*4096], d_outWf_l[3*32*4096];  // padded 32 frags

// ---------------- fragment-layout activations ----------------
__device__ unsigned d_h1f_h [3*ASLAB], d_h1f_l [3*ASLAB];
__device__ unsigned d_h2f_h [3*ASLAB], d_h2f_l [3*ASLAB];
__device__ unsigned d_ctxf_h[3*ASLAB], d_ctxf_l[3*ASLAB];
__device__ unsigned d_uof_h [3*ASLAB], d_uof_l [3*ASLAB];
__device__ unsigned d_unf_h [2*ASLAB], d_unf_l [2*ASLAB];

// ---------------- grid barrier (replay-safe, sense via generation) ----------
__device__ unsigned int g_arrive;
__device__ unsigned int g_gen;

__device__ __forceinline__ void gsync()
{
    __threadfence();
    __syncthreads();
    if (threadIdx.x == 0) {
        volatile unsigned int* vg = &g_gen;
        unsigned int g = *vg;
        if (atomicAdd(&g_arrive, 1u) == (unsigned)(gridDim.x - 1)) {
            g_arrive = 0;
            __threadfence();
            *vg = g + 1u;
        } else {
            while (*vg == g) __nanosleep(32);
        }
        __threadfence();
    }
    __syncthreads();
}

// ---------------- f32x2 helpers (preamble FFMA2 path) ----------------
__device__ __forceinline__ void fma2(unsigned long long &c, unsigned long long a,
                                     unsigned long long b) {
    asm("fma.rn.f32x2 %0, %1, %2, %0;" : "+l"(c) : "l"(a), "l"(b));
}
__device__ __forceinline__ void unpack2(unsigned long long v, float &lo, float &hi) {
    asm("mov.b64 {%0, %1}, %2;" : "=f"(lo), "=f"(hi) : "l"(v));
}
__device__ __forceinline__ unsigned long long dup2(float a) {
    unsigned long long r;
    asm("mov.b64 %0, {%1, %1};" : "=l"(r) : "f"(a));
    return r;
}

// ---------------- mma / async helpers ----------------
__device__ __forceinline__ void mma16816(float* d, const unsigned* a, const unsigned* b) {
    asm volatile("mma.sync.aligned.m16n8k16.row.col.f32.bf16.bf16.f32 "
                 "{%0,%1,%2,%3},{%4,%5,%6,%7},{%8,%9},{%0,%1,%2,%3};"
                 : "+f"(d[0]), "+f"(d[1]), "+f"(d[2]), "+f"(d[3])
                 : "r"(a[0]), "r"(a[1]), "r"(a[2]), "r"(a[3]), "r"(b[0]), "r"(b[1]));
}
__device__ __forceinline__ uint2 lds64(unsigned a) {
    uint2 r;
    asm volatile("ld.shared.v2.u32 {%0,%1},[%2];" : "=r"(r.x), "=r"(r.y) : "r"(a));
    return r;
}
__device__ __forceinline__ void cpasync16(unsigned dst, const void* src) {
    asm volatile("cp.async.cg.shared.global [%0],[%1],16;" :: "r"(dst), "l"(src) : "memory");
}
__device__ __forceinline__ void cpcommit() {
    asm volatile("cp.async.commit_group;" ::: "memory");
}
__device__ __forceinline__ void cpwait2() {
    asm volatile("cp.async.wait_group 2;" ::: "memory");
}

// ---------------- split/pack helpers ----------------
__device__ __forceinline__ void pack_split(float v0, float v1, unsigned& hi, unsigned& lo)
{
    __nv_bfloat16 h0 = __float2bfloat16(v0);
    __nv_bfloat16 h1 = __float2bfloat16(v1);
    __nv_bfloat16 l0 = __float2bfloat16(v0 - __bfloat162float(h0));
    __nv_bfloat16 l1 = __float2bfloat16(v1 - __bfloat162float(h1));
    hi = (unsigned)__bfloat16_as_ushort(h0) | ((unsigned)__bfloat16_as_ushort(h1) << 16);
    lo = (unsigned)__bfloat16_as_ushort(l0) | ((unsigned)__bfloat16_as_ushort(l1) << 16);
}

__device__ __forceinline__ float gatef(float gi, float gg, float go)
{
    float si = 1.f / (1.f + expf(-gi));
    float so = 1.f / (1.f + expf(-go));
    return so * tanhf(si * tanhf(gg));
}

// ================= preamble FFMA2 GEMM (512-thread) =================
struct GP {
    const float* A;  long long lda,  Az;
    const float* B;  long long ldb,  Bz;
    int K, M, N, zc, compact, epi;
    float* C; long long ldc, Cz;
    const float* bias; long long biasz; int biasCompact;
};

__device__ __forceinline__ void run_mm(const float* A, long long lda, int M, int m0,
                                       const float* Bb, long long ldb, int N, int n0, int K,
                                       float* As, float* Bs,
                                       unsigned long long (*acc)[4],
                                       int tid, int tx, int ty)
{
    int nIter = K >> 4;
    int row = tid >> 2, kq = (tid & 3) << 2;
    for (int it = 0; it < nIter; it++) {
        int k0 = it << 4;
        float4 ra = (m0 + row < M)
            ? *(const float4*)(A + (long long)(m0 + row) * lda + k0 + kq)
            : make_float4(0.f, 0.f, 0.f, 0.f);
        float4 rb = (n0 + row < N)
            ? *(const float4*)(Bb + (long long)row * ldb + k0 + kq)
            : make_float4(0.f, 0.f, 0.f, 0.f);
        __syncthreads();
        As[(kq + 0) * 128 + row] = ra.x;
        As[(kq + 1) * 128 + row] = ra.y;
        As[(kq + 2) * 128 + row] = ra.z;
        As[(kq + 3) * 128 + row] = ra.w;
        Bs[(kq + 0) * 128 + row] = rb.x;
        Bs[(kq + 1) * 128 + row] = rb.y;
        Bs[(kq + 2) * 128 + row] = rb.z;
        Bs[(kq + 3) * 128 + row] = rb.w;
        __syncthreads();
#pragma unroll
        for (int kk = 0; kk < 16; kk++) {
            ulonglong2 b01 = *(const ulonglong2*)&Bs[kk * 128 + tx * 8];
            ulonglong2 b23 = *(const ulonglong2*)&Bs[kk * 128 + tx * 8 + 4];
            ulonglong2 ap  = *(const ulonglong2*)&As[kk * 128 + ty * 4];
            float av[4];
            unpack2(ap.x, av[0], av[1]);
            unpack2(ap.y, av[2], av[3]);
#pragma unroll
            for (int mi = 0; mi < 4; mi++) {
                unsigned long long a2 = dup2(av[mi]);
                fma2(acc[mi][0], b01.x, a2);
                fma2(acc[mi][1], b01.y, a2);
                fma2(acc[mi][2], b23.x, a2);
                fma2(acc[mi][3], b23.y, a2);
            }
        }
    }
    __syncthreads();
}

__device__ void gemm_stage(const GP& g, float* As, float* Bs)
{
    int mT = (g.M + 127) >> 7;
    int nT = (g.N + 127) >> 7;
    int total = g.zc * mT * nT;
    int tid = threadIdx.x;
    int tx = tid & 15, ty = tid >> 4;

    for (int tile = blockIdx.x; tile < total; tile += gridDim.x) {
        int z  = tile / (mT * nT);
        int r  = tile - z * (mT * nT);
        int m0 = (r / nT) << 7;
        int n0 = (r % nT) << 7;
        int noff = (g.compact && n0 >= 1024) ? 1024 : 0;

        unsigned long long acc[4][4];
#pragma unroll
        for (int i = 0; i < 4; i++)
#pragma unroll
            for (int j = 0; j < 4; j++) acc[i][j] = 0ull;

        const float* A  = g.A + (long long)z * g.Az;
        const float* Bb = g.B + (long long)z * g.Bz + (long long)(n0 + noff) * g.ldb;
        run_mm(A, g.lda, g.M, m0, Bb, g.ldb, g.N, n0, g.K, As, Bs, acc, tid, tx, ty);

        float* C = g.C + (long long)z * g.Cz;
#pragma unroll
        for (int mi = 0; mi < 4; mi++) {
            int m = m0 + ty * 4 + mi;
            if (m >= g.M) continue;
            float cv[8];
#pragma unroll
            for (int jj = 0; jj < 4; jj++)
                unpack2(acc[mi][jj], cv[2 * jj], cv[2 * jj + 1]);
#pragma unroll
            for (int nj = 0; nj < 8; nj++) {
                int n = n0 + tx * 8 + nj;
                if (n >= g.N) continue;
                float v = cv[nj];
                if (g.bias) v += g.bias[(long long)z * g.biasz + (g.biasCompact ? (n + noff) : n)];
                if (g.epi == 1) v = tanhf(v);
                C[(long long)m * g.ldc + n] = v;
            }
        }
    }
}

// ================= fragment-direct tensor-core GEMM (cp.async B pipeline) ==
// A frag slab layout: uint index = ((mf*64 + ks)*32 + lane)*4 + reg
// B frag layout:      uint index = ((nf*64 + ks)*64 + lane*2 + reg)
// smem B staging: 4 stages x 8KB; stage = hi 4KB | lo 4KB; word (f*64 + w)
struct MGP {
    const unsigned *Ah, *Al;   long long Az;
    const unsigned *Bh, *Bl;   long long Bz;
    const unsigned *A2h, *A2l; long long A2z;
    const unsigned *B2h, *B2l; long long B2z;
    int M, N, zc;                               // K fixed = 1024 (64 slices)
    float* C; long long ldc, Cz;
    const float* add0; long long add0z;
    const float *add1, *add2;
    const float* bias; long long biasz; int biasCompact;
    const float* Eg;  long long Egz;
    const int*  tok;  long long tokz;  int tokstride;
};

template<int TM>
__device__ __forceinline__ void mma_runp(
    const unsigned* Ah, const unsigned* Al,
    const unsigned* Bh, const unsigned* Bl,
    int m0, int n0, float* d, unsigned sb, int tid, int wm, int wn, int L)
{
    constexpr int NT = (TM == 128) ? 4 : 2;
    int mf0 = (m0 >> 4) + wm * 2;
    const unsigned* paH0 = Ah + ((long long)(mf0 + 0) * 64) * 128 + L * 4;
    const unsigned* paH1 = Ah + ((long long)(mf0 + 1) * 64) * 128 + L * 4;
    const unsigned* paL0 = Al + ((long long)(mf0 + 0) * 64) * 128 + L * 4;
    const unsigned* paL1 = Al + ((long long)(mf0 + 1) * 64) * 128 + L * 4;

    // B staging: threads 0..255 copy hi, 256..511 copy lo; one 16B chunk each.
    bool hiH = tid < 256;
    int st = hiH ? tid : tid - 256;
    int sf = st >> 4, wq = (st & 15) * 4;
    const unsigned* gB = (hiH ? Bh : Bl) + ((long long)((n0 >> 3) + sf) * 64) * 64 + wq;
    unsigned dstB = sb + (hiH ? 0u : 4096u) + (unsigned)((sf * 64 + wq) * 4);

#pragma unroll
    for (int s = 0; s < 3; s++) {               // prologue: stages 0..2
        cpasync16(dstB + s * 8192u, gB + s * 64);
        cpcommit();
    }
    uint4 ahC0 = *(const uint4*)(paH0);
    uint4 ahC1 = *(const uint4*)(paH1);
    uint4 alC0 = *(const uint4*)(paL0);
    uint4 alC1 = *(const uint4*)(paL1);

    for (int ks = 0; ks < 64; ks++) {
        cpwait2();                              // stage ks complete (pending <= 2)
        __syncthreads();                        // visibility + reuse safety
        if (ks + 3 < 64)
            cpasync16(dstB + (unsigned)(((ks + 3) & 3) * 8192) + 0u, gB + (ks + 3) * 64);
        cpcommit();                             // always: keeps group indices aligned

        unsigned sBase = sb + (unsigned)((ks & 3) * 8192);
        uint2 bh[NT], bl[NT];
#pragma unroll
        for (int nt = 0; nt < NT; nt++) {
            unsigned f = (unsigned)(((wn * NT + nt) * 64 + L * 2) * 4);
            bh[nt] = lds64(sBase + f);
            bl[nt] = lds64(sBase + 4096u + f);
        }
        uint4 ah0 = ahC0, ah1 = ahC1, al0 = alC0, al1 = alC1;
        if (ks < 63) {                          // register-prefetch next A slice
            ahC0 = *(const uint4*)(paH0 + (ks + 1) * 128);
            ahC1 = *(const uint4*)(paH1 + (ks + 1) * 128);
            alC0 = *(const uint4*)(paL0 + (ks + 1) * 128);
            alC1 = *(const uint4*)(paL1 + (ks + 1) * 128);
        }
#pragma unroll
        for (int nt = 0; nt < NT; nt++) {
            float* d0 = d + nt * 4;
            float* d1 = d + (NT + nt) * 4;
            mma16816(d0, (const unsigned*)&ah0, (const unsigned*)&bh[nt]);
            mma16816(d0, (const unsigned*)&ah0, (const unsigned*)&bl[nt]);
            mma16816(d0, (const unsigned*)&al0, (const unsigned*)&bh[nt]);
            mma16816(d1, (const unsigned*)&ah1, (const unsigned*)&bh[nt]);
            mma16816(d1, (const unsigned*)&ah1, (const unsigned*)&bl[nt]);
            mma16816(d1, (const unsigned*)&al1, (const unsigned*)&bh[nt]);
        }
    }
}

template<int TM>
__device__ void mma_stage(const MGP& g, unsigned sb)
{
    constexpr int NT = (TM == 128) ? 4 : 2;
    constexpr int NW = NT * 8;
    int mT = (g.M + TM - 1) / TM;
    int nT = (g.N + 127) >> 7;
    int total = g.zc * mT * nT;
    int tid = threadIdx.x, w = tid >> 5, L = tid & 31;
    int wm = (TM == 128) ? (w >> 2) : (w >> 3);
    int wn = (TM == 128) ? (w & 3) : (w & 7);

    for (int tile = blockIdx.x; tile < total; tile += gridDim.x) {
        int z  = tile / (mT * nT);
        int r  = tile - z * (mT * nT);
        int m0 = (r / nT) * TM;
        int n0 = (r % nT) << 7;

        float d[2 * NT * 4];
#pragma unroll
        for (int i = 0; i < 2 * NT * 4; i++) d[i] = 0.f;

        mma_runp<TM>(g.Ah + (long long)z * g.Az, g.Al + (long long)z * g.Az,
                     g.Bh + (long long)z * g.Bz, g.Bl + (long long)z * g.Bz,
                     m0, n0, d, sb, tid, wm, wn, L);
        if (g.A2h)
            mma_runp<TM>(g.A2h + (long long)z * g.A2z, g.A2l + (long long)z * g.A2z,
                         g.B2h + (long long)z * g.B2z, g.B2l + (long long)z * g.B2z,
                         m0, n0, d, sb, tid, wm, wn, L);

        float* C = g.C + (long long)z * g.Cz;
#pragma unroll
        for (int mt = 0; mt < 2; mt++) {
            int rbase = m0 + wm * 32 + mt * 16 + (L >> 2);
            int tk0 = 0, tk1 = 0;
            if (g.Eg) {
                tk0 = g.tok[(long long)z * g.tokz + (long long)rbase * g.tokstride];
                tk1 = g.tok[(long long)z * g.tokz + (long long)(rbase + 8) * g.tokstride];
            }
#pragma unroll
            for (int nt = 0; nt < NT; nt++) {
                const float* dd = d + (mt * NT + nt) * 4;
                int cbase = n0 + wn * NW + nt * 8 + (L & 3) * 2;
#pragma unroll
                for (int e = 0; e < 4; e++) {
                    int m = rbase + (e >= 2 ? 8 : 0);
                    int n = cbase + (e & 1);
                    if (n >= g.N || m >= g.M) continue;
                    float v = dd[e];
                    if (g.add0) v += g.add0[(long long)z * g.add0z + (long long)m * g.N + n];
                    if (g.add1) v += g.add1[(long long)m * g.N + n];
                    if (g.add2) v += g.add2[(long long)m * g.N + n];
                    if (g.bias) {
                        int nf = g.biasCompact ? (n + (n >= 1024 ? 1024 : 0)) : n;
                        v += g.bias[(long long)z * g.biasz + nf];
                    }
                    if (g.Eg)
                        v += g.Eg[(long long)z * g.Egz +
                                  (long long)(e >= 2 ? tk1 : tk0) * g.N + n];
                    C[(long long)m * g.ldc + n] = v;
                }
            }
        }
    }
}

// ---------------- elementwise stages (fragment writers) ----------------
__device__ void gate_stagef(const float* gsrc, long long gz, int zc,
                            unsigned* d0h, unsigned* d0l,
                            unsigned* d1h, unsigned* d1l)
{
    int total = zc * ASLAB;
    for (int idx = blockIdx.x * NTHR + threadIdx.x; idx < total; idx += gridDim.x * NTHR) {
        int u = idx & (ASLAB - 1);
        int z = idx >> 17;
        int r = u & 3, l = (u >> 2) & 31, ks = (u >> 7) & 63, mf = u >> 13;
        int m  = mf * 16 + (l >> 2) + (r & 1) * 8;
        int k0 = ks * 16 + ((r >> 1) & 1) * 8 + (l & 3) * 2;
        const float* gp = gsrc + (long long)z * gz + (long long)m * NC;
        float v0 = gatef(gp[k0],     gp[1024 + k0],     gp[2048 + k0]);
        float v1 = gatef(gp[k0 + 1], gp[1024 + k0 + 1], gp[2048 + k0 + 1]);
        unsigned hi, lo;
        pack_split(v0, v1, hi, lo);
        d0h[(long long)z * ASLAB + u] = hi;
        d0l[(long long)z * ASLAB + u] = lo;
        if (d1h) {
            d1h[(long long)z * ASLAB + u] = hi;
            d1l[(long long)z * ASLAB + u] = lo;
        }
    }
}

__device__ void reset_stagef(const float* hid)
{
    for (int u = blockIdx.x * NTHR + threadIdx.x; u < ASLAB; u += gridDim.x * NTHR) {
        int r = u & 3, l = (u >> 2) & 31, ks = (u >> 7) & 63, mf = u >> 13;
        int m  = mf * 16 + (l >> 2) + (r & 1) * 8;
        int k0 = ks * 16 + ((r >> 1) & 1) * 8 + (l & 3) * 2;
        const float* hp = hid + (long long)m * 1024 + k0;
        unsigned hi, lo;
        pack_split(hp[0], hp[1], hi, lo);
#pragma unroll
        for (int z = 0; z < 3; z++) {
            d_h1f_h[z * ASLAB + u] = hi; d_h1f_l[z * ASLAB + u] = lo;
            d_h2f_h[z * ASLAB + u] = hi; d_h2f_l[z * ASLAB + u] = lo;
        }
        d_ctxf_h[2 * ASLAB + u] = hi; d_ctxf_l[2 * ASLAB + u] = lo;
    }
}

__device__ void prep_stage(const float* c)
{
    for (int idx = blockIdx.x * NTHR + threadIdx.x; idx < (16 * 256 * 512);
         idx += gridDim.x * NTHR) {
        int ptr = idx >> 17;
        int rem = idx & 131071;
        int b = rem >> 9, k = rem & 511;
        d_cT[idx] = c[((b << 4) + ptr) * 512 + k];
        int pm = ptr > 0 ? ptr - 1 : 0;
        d_cPrev[idx] = c[((b << 4) + pm) * 512 + k];
    }
}

__device__ void nb1_stage(const float* emb, const float* W1ih, const float* b1)
{
    for (int idx = blockIdx.x * NTHR + threadIdx.x; idx < 3 * 3072;
         idx += gridDim.x * NTHR) {
        int i = idx / 3072, n = idx - (idx / 3072) * 3072;
        int nfull = n + (n >= 1024 ? 1024 : 0);
        const float* e = emb + (long long)i * 130 * 512;            // v = 0 row
        const float* w = W1ih + ((long long)i * 4096 + nfull) * 1024;
        float s = b1[i * 4096 + nfull];
        for (int k = 0; k < 512; k++) s += e[k] * w[k];
        d_nb1[idx] = s;
    }
}

__device__ void convw_frag(const float* src, long long sld, long long sz, int kstep,
                           int zc, int Nvalid, int NF, int compact,
                           unsigned* H, unsigned* Lo)
{
    int total = zc * NF * 4096;
    for (int idx = blockIdx.x * NTHR + threadIdx.x; idx < total;
         idx += gridDim.x * NTHR) {
        int r  = idx & 1;
        int l  = (idx >> 1) & 31;
        int ks = (idx >> 6) & 63;
        int rest = idx >> 12;
        int nf = rest % NF, z = rest / NF;
        int n = nf * 8 + (l >> 2);
        int k = ks * 16 + r * 8 + (l & 3) * 2;
        float v0 = 0.f, v1 = 0.f;
        if (n < Nvalid) {
            int nfull = compact ? (n + (n >= 1024 ? 1024 : 0)) : n;
            const float* p = src + (long long)z * sz + (long long)nfull * sld
                           + k + (long long)z * kstep;
            v0 = p[0]; v1 = p[1];
        }
        unsigned hi, lo;
        pack_split(v0, v1, hi, lo);
        H[idx] = hi; Lo[idx] = lo;
    }
}

// ---------------- the single persistent kernel ----------------
__global__ void __launch_bounds__(NTHR, 1)
mega_kernel(const float* c, const float* W1ih, const float* W1hh, const float* b1,
            const float* cWih, const float* cWhh, const float* cb,
            const float* W2ih, const float* W2hh, const float* b2,
            const float* outW, const float* outb,
            const float* hidW, const float* hidb,
            const float* emb, const int* tgt, float* out)
{
    __shared__ __align__(16) char smem_raw[32768];  // B pipeline (4x8KB) / preamble
    float* As = (float*)smem_raw;
    float* Bs = (float*)(smem_raw + 8192);
    unsigned sb;
    asm("{.reg .u64 t; cvta.to.shared.u64 t, %1; cvt.u32.u64 %0, t;}"
        : "=r"(sb) : "l"(smem_raw));

    // ---- phase 0: transpose + notes0 hoist + weight fragment conversion ----
    prep_stage(c);
    nb1_stage(emb, W1ih, b1);
    convw_frag(W1hh, 1024, 4096LL * 1024, 0,    3, 3072, WNF, 1, d_W1hhf_h, d_W1hhf_l);
    convw_frag(cWih, 3072, 0,             1024, 3, 3072, WNF, 1, d_cWihf_h, d_cWihf_l);
    convw_frag(cWhh, 1024, 0,             0,    1, 3072, WNF, 1, d_cWhhf_h, d_cWhhf_l);
    convw_frag(W2ih, 1536, 4096LL * 1536, 0,    3, 3072, WNF, 1, d_W2ihf_h, d_W2ihf_l);
    convw_frag(W2hh, 1024, 4096LL * 1024, 0,    3, 3072, WNF, 1, d_W2hhf_h, d_W2hhf_l);
    convw_frag(outW, 1024, 130LL * 1024,  0,    3, 130,  32,  0, d_outWf_h, d_outWf_l);
    gsync();

    // ---- phase 1: per-bar hoisted GEMMs (FFMA2 path) ----
    { GP g = {};
        g.A = d_cPrev; g.lda = 512; g.B = hidW; g.ldb = 512;
        g.K = 512; g.M = 4096; g.N = 1024; g.zc = 1; g.epi = 1;
        g.C = d_hid; g.ldc = 1024; g.bias = hidb;
        gemm_stage(g, As, Bs); }
    { GP g = {};
        g.A = d_cT; g.lda = 512;
        g.B = W1ih + 512; g.ldb = 1024; g.Bz = 4096LL * 1024;
        g.K = 512; g.M = 4096; g.N = NC; g.zc = 3; g.compact = 1;
        g.C = d_A1; g.ldc = NC; g.Cz = 16LL * GS;
        g.bias = d_nb1; g.biasz = NC;
        gemm_stage(g, As, Bs); }
    { GP g = {};
        g.A = d_cT; g.lda = 512;
        g.B = W1ih + 4096LL * 1024 + 512; g.ldb = 1024;
        g.K = 512; g.M = 4096; g.N = NC; g.zc = 1; g.compact = 1;
        g.C = d_CU; g.ldc = NC;
        g.bias = b1 + 4096; g.biasCompact = 1;
        gemm_stage(g, As, Bs); }
    { GP g = {};
        g.A = d_cT; g.lda = 512;
        g.B = W2ih + 1024; g.ldb = 1536; g.Bz = 4096LL * 1536;
        g.K = 512; g.M = 4096; g.N = NC; g.zc = 3; g.compact = 1;
        g.C = d_C2; g.ldc = NC; g.Cz = 16LL * GS;
        g.bias = b2; g.biasz = 4096; g.biasCompact = 1;
        gemm_stage(g, As, Bs); }
    { GP g = {};
        g.A = emb; g.lda = 512;
        g.B = W1ih + 4096LL * 1024; g.ldb = 1024;
        g.K = 512; g.M = 390; g.N = NC; g.zc = 1; g.compact = 1;
        g.C = d_E; g.ldc = NC;
        gemm_stage(g, As, Bs); }
    gsync();

    // ---- time loop (cp.async pipelined tensor-core path) ----
    for (int t = 0; t < TT; t++) {
        int ptr = t >> 4;
        if ((t & 15) == 0) {
            reset_stagef(d_hid + (long long)ptr * BH);
            gsync();
        }

        { // g = A1[.,ptr] + h1 @ W1hh^T
            MGP g = {};
            g.Ah = d_h1f_h; g.Al = d_h1f_l; g.Az = ASLAB;
            g.Bh = d_W1hhf_h; g.Bl = d_W1hhf_l; g.Bz = WZS;
            g.M = BB; g.N = NC; g.zc = 3;
            g.C = d_g; g.ldc = NC; g.Cz = GS;
            g.add0 = d_A1 + (long long)ptr * GS; g.add0z = 16LL * GS;
            mma_stage<128>(g, sb);
        }
        gsync();
        gate_stagef(d_g, GS, 3, d_h1f_h, d_h1f_l, d_uof_h, d_uof_l);
        gsync();

        { // s[i] = uold[i] @ cWih[:, i*1024:]^T
            MGP g = {};
            g.Ah = d_uof_h; g.Al = d_uof_l; g.Az = ASLAB;
            g.Bh = d_cWihf_h; g.Bl = d_cWihf_l; g.Bz = WZS;
            g.M = BB; g.N = NC; g.zc = 3;
            g.C = d_s; g.ldc = NC; g.Cz = GS;
            mma_stage<128>(g, sb);
        }
        { // gu[i] = E[i][tok] + CU[ptr] + uold[i] @ W1hh[1]^T   (i = 0,1)
            MGP g = {};
            g.Ah = d_uof_h; g.Al = d_uof_l; g.Az = ASLAB;
            g.Bh = d_W1hhf_h + 1LL * WZS; g.Bl = d_W1hhf_l + 1LL * WZS; g.Bz = 0;
            g.M = BB; g.N = NC; g.zc = 2;
            g.C = d_g; g.ldc = NC; g.Cz = GS;
            g.add0 = d_CU + (long long)ptr * GS; g.add0z = 0;
            g.Eg = d_E; g.Egz = 130LL * NC;
            g.tok = tgt + t; g.tokz = 65536; g.tokstride = 256;
            mma_stage<128>(g, sb);
        }
        gsync();
        gate_stagef(d_g, GS, 2, d_unf_h, d_unf_l, (unsigned*)0, (unsigned*)0);
        gsync();

        { // sn[i] = unew[i] @ cWih[:, i*1024:]^T  (i = 0,1)
            MGP g = {};
            g.Ah = d_unf_h; g.Al = d_unf_l; g.Az = ASLAB;
            g.Bh = d_cWihf_h; g.Bl = d_cWihf_l; g.Bz = WZS;
            g.M = BB; g.N = NC; g.zc = 2;
            g.C = d_sn; g.ldc = NC; g.Cz = GS;
            mma_stage<128>(g, sb);
        }
        { // ctx update 0
            MGP g = {};
            g.Ah = d_ctxf_h + 2LL * ASLAB; g.Al = d_ctxf_l + 2LL * ASLAB; g.Az = 0;
            g.Bh = d_cWhhf_h; g.Bl = d_cWhhf_l; g.Bz = 0;
            g.M = BB; g.N = NC; g.zc = 1;
            g.C = d_g; g.ldc = NC; g.Cz = 0;
            g.add0 = d_s; g.add0z = 0;
            g.add1 = d_s + GS; g.add2 = d_s + 2LL * GS;
            g.bias = cb; g.biasz = 0; g.biasCompact = 1;
            mma_stage<64>(g, sb);
        }
        gsync();
        gate_stagef(d_g, 0, 1, d_ctxf_h, d_ctxf_l, (unsigned*)0, (unsigned*)0);
        gsync();

        { // ctx update 1
            MGP g = {};
            g.Ah = d_ctxf_h; g.Al = d_ctxf_l; g.Az = 0;
            g.Bh = d_cWhhf_h; g.Bl = d_cWhhf_l; g.Bz = 0;
            g.M = BB; g.N = NC; g.zc = 1;
            g.C = d_g; g.ldc = NC; g.Cz = 0;
            g.add0 = d_sn; g.add0z = 0;
            g.add1 = d_s + GS; g.add2 = d_s + 2LL * GS;
            g.bias = cb; g.biasz = 0; g.biasCompact = 1;
            mma_stage<64>(g, sb);
        }
        gsync();
        gate_stagef(d_g, 0, 1, d_ctxf_h + ASLAB, d_ctxf_l + ASLAB,
                    (unsigned*)0, (unsigned*)0);
        gsync();

        { // ctx update 2
            MGP g = {};
            g.Ah = d_ctxf_h + 1LL * ASLAB; g.Al = d_ctxf_l + 1LL * ASLAB; g.Az = 0;
            g.Bh = d_cWhhf_h; g.Bl = d_cWhhf_l; g.Bz = 0;
            g.M = BB; g.N = NC; g.zc = 1;
            g.C = d_g; g.ldc = NC; g.Cz = 0;
            g.add0 = d_sn; g.add0z = 0;
            g.add1 = d_sn + GS; g.add2 = d_s + 2LL * GS;
            g.bias = cb; g.biasz = 0; g.biasCompact = 1;
            mma_stage<64>(g, sb);
        }
        gsync();
        gate_stagef(d_g, 0, 1, d_ctxf_h + 2LL * ASLAB, d_ctxf_l + 2LL * ASLAB,
                    (unsigned*)0, (unsigned*)0);
        gsync();

        { // g2[i] = ctx[i] @ W2ih[i][:, :1024]^T + h2[i] @ W2hh[i]^T + C2[i][ptr]
            MGP g = {};
            g.Ah = d_ctxf_h; g.Al = d_ctxf_l; g.Az = ASLAB;
            g.Bh = d_W2ihf_h; g.Bl = d_W2ihf_l; g.Bz = WZS;
            g.A2h = d_h2f_h; g.A2l = d_h2f_l; g.A2z = ASLAB;
            g.B2h = d_W2hhf_h; g.B2l = d_W2hhf_l; g.B2z = WZS;
            g.M = BB; g.N = NC; g.zc = 3;
            g.C = d_g; g.ldc = NC; g.Cz = GS;
            g.add0 = d_C2 + (long long)ptr * GS; g.add0z = 16LL * GS;
            mma_stage<128>(g, sb);
        }
        gsync();
        gate_stagef(d_g, GS, 3, d_h2f_h, d_h2f_l, (unsigned*)0, (unsigned*)0);
        gsync();

        { // out[i][:,t,:] = (uold[i] + h2[i]) @ outW[i]^T + outb[i]
            MGP g = {};
            g.Ah = d_uof_h; g.Al = d_uof_l; g.Az = ASLAB;
            g.Bh = d_outWf_h; g.Bl = d_outWf_l; g.Bz = 32LL * 4096;
            g.A2h = d_h2f_h; g.A2l = d_h2f_l; g.A2z = ASLAB;
            g.B2h = d_outWf_h; g.B2l = d_outWf_l; g.B2z = 32LL * 4096;
            g.M = BB; g.N = VV; g.zc = 3;
            g.C = out + (long long)t * VV; g.ldc = (long long)TT * VV;
            g.Cz = (long long)BB * TT * VV;
            g.bias = outb; g.biasz = VV;
            mma_stage<64>(g, sb);
        }
        gsync();
    }
}

// ---------------- host ----------------
extern "C" void kernel_launch(void* const* d_in, const int* in_sizes, int n_in,
                              void* d_out, int out_size)
{
    (void)in_sizes; (void)n_in; (void)out_size;
    mega_kernel<<<NBLK, NTHR>>>(
        (const float*)d_in[0],  (const float*)d_in[1],  (const float*)d_in[2],
        (const float*)d_in[3],  (const float*)d_in[4],  (const float*)d_in[5],
        (const float*)d_in[6],  (const float*)d_in[7],  (const float*)d_in[8],
        (const float*)d_in[9],  (const float*)d_in[10], (const float*)d_in[11],
        (const float*)d_in[12], (const float*)d_in[13], (const float*)d_in[14],
        (const int*)d_in[15],   (float*)d_out);
}